// round 11
// baseline (speedup 1.0000x reference)
#include <cuda_runtime.h>

#define NT    8192
#define KT    200
#define CINC  512
#define HIDC  256
#define COUTC 40
#define EE    5
#define MHD   64
#define TGRID 4096
#define TBL_LO (-8.0f)
#define TBL_HI ( 8.0f)
#define P132  132
#define PKA   20

// ---------------- scratch ----------------
__device__ float d_ftable[EE * TGRID];
__device__ float d_Vsum[KT];
__device__ float d_Tm[KT * CINC];       // T = U^T X   [200 x 512]
__device__ float d_P[KT * HIDC];        // P = T @ Ww  [200 x 256]
__device__ float d_colsum[HIDC], d_colsq[HIDC];

// bf16 split-2: (v0,v1) -> hi bf16x2 + lo bf16x2 (lo = residual); v0 in lo16, v1 in hi16
__device__ __forceinline__ void bsplit(unsigned& hi, unsigned& lo, float v0, float v1) {
    unsigned h;
    asm("cvt.rn.bf16x2.f32 %0, %1, %2;" : "=r"(h) : "f"(v1), "f"(v0));
    float r0 = v0 - __uint_as_float(h << 16);
    float r1 = v1 - __uint_as_float(h & 0xffff0000u);
    unsigned l;
    asm("cvt.rn.bf16x2.f32 %0, %1, %2;" : "=r"(l) : "f"(r1), "f"(r0));
    hi = h; lo = l;
}

__device__ __forceinline__ void mma_bf16(float* c, const unsigned* a, const unsigned* b) {
    asm volatile(
        "mma.sync.aligned.m16n8k16.row.col.f32.bf16.bf16.f32 "
        "{%0,%1,%2,%3},{%4,%5,%6,%7},{%8,%9},{%0,%1,%2,%3};"
        : "+f"(c[0]), "+f"(c[1]), "+f"(c[2]), "+f"(c[3])
        : "r"(a[0]), "r"(a[1]), "r"(a[2]), "r"(a[3]), "r"(b[0]), "r"(b[1]));
}

__device__ __forceinline__ unsigned smem_u32(const void* p) {
    return (unsigned)__cvta_generic_to_shared(p);
}
__device__ __forceinline__ void cpa16(unsigned dst, const void* src, int nbytes) {
    asm volatile("cp.async.cg.shared.global [%0], [%1], 16, %2;\n"
                 :: "r"(dst), "l"(src), "r"(nbytes));
}
#define CP_COMMIT() asm volatile("cp.async.commit_group;\n" ::: "memory")
#define CP_WAIT1()  asm volatile("cp.async.wait_group 1;\n" ::: "memory")
#define CP_WAIT0()  asm volatile("cp.async.wait_group 0;\n" ::: "memory")

// ---------------- tables (+ fused zeroing) ----------------
__global__ void k_table(const float* __restrict__ eW1, const float* __restrict__ eb1,
                        const float* __restrict__ eW2, const float* __restrict__ eb2,
                        const float* __restrict__ eW3, const float* __restrict__ eb3) {
    int gid = (blockIdx.y * gridDim.x + blockIdx.x) * blockDim.x + threadIdx.x;
    int nthr = gridDim.x * gridDim.y * blockDim.x;
    for (int i = gid; i < KT * CINC; i += nthr) d_Tm[i] = 0.f;
    if (gid < KT) d_Vsum[gid] = 0.f;
    if (gid < HIDC) { d_colsum[gid] = 0.f; d_colsq[gid] = 0.f; }

    int e = blockIdx.y;
    __shared__ float W2s[MHD * MHD];
    __shared__ float W1s[MHD], b1s[MHD], b2s[MHD], W3s[MHD];
    for (int i = threadIdx.x; i < MHD * MHD; i += blockDim.x) W2s[i] = eW2[e * MHD * MHD + i];
    if (threadIdx.x < MHD) {
        W1s[threadIdx.x] = eW1[e * MHD + threadIdx.x];
        b1s[threadIdx.x] = eb1[e * MHD + threadIdx.x];
        b2s[threadIdx.x] = eb2[e * MHD + threadIdx.x];
        W3s[threadIdx.x] = eW3[e * MHD + threadIdx.x];
    }
    __syncthreads();

    int t = blockIdx.x * blockDim.x + threadIdx.x;
    float x = TBL_LO + (TBL_HI - TBL_LO) * ((float)t / (float)(TGRID - 1));

    float h1[MHD];
#pragma unroll
    for (int h = 0; h < MHD; h++) h1[h] = fmaxf(fmaf(x, W1s[h], b1s[h]), 0.f);

    float v = eb3[e];
    for (int j = 0; j < MHD; j += 4) {
        float a0 = b2s[j], a1 = b2s[j + 1], a2 = b2s[j + 2], a3 = b2s[j + 3];
#pragma unroll
        for (int h = 0; h < MHD; h++) {
            float hv = h1[h];
            float4 w = *(const float4*)&W2s[h * MHD + j];
            a0 = fmaf(hv, w.x, a0);
            a1 = fmaf(hv, w.y, a1);
            a2 = fmaf(hv, w.z, a2);
            a3 = fmaf(hv, w.w, a3);
        }
        v = fmaf(fmaxf(a0, 0.f), W3s[j],     v);
        v = fmaf(fmaxf(a1, 0.f), W3s[j + 1], v);
        v = fmaf(fmaxf(a2, 0.f), W3s[j + 2], v);
        v = fmaf(fmaxf(a3, 0.f), W3s[j + 3], v);
    }
    d_ftable[e * TGRID + t] = v;
}

// ---------------- Vsum[col] = sum_n lerp(f_e, U[n,col]) ----------------
__global__ void k_reduceV(const float* __restrict__ U) {
    int col = threadIdx.x;
    if (col >= KT) return;
    int e = col / 40;
    const float* tbl = d_ftable + e * TGRID;
    const float scale = (float)(TGRID - 1) / (TBL_HI - TBL_LO);
    int n0 = blockIdx.x * 64;

    float sum = 0.f;
    for (int n = n0; n < n0 + 64; n++) {
        float u  = U[n * KT + col];
        float xi = (u - TBL_LO) * scale;
        xi = fminf(fmaxf(xi, 0.f), (float)(TGRID - 2) + 0.9999f);
        int   i  = (int)xi;
        float fr = xi - (float)i;
        float a = tbl[i], b = tbl[i + 1];
        sum += fmaf(fr, b - a, a);
    }
    atomicAdd(&d_Vsum[col], sum);
}

// ============ T = U^T @ X : bf16-split3 m16n8k16, 3-stage cp.async, 1 barrier/iter ============
// grid (2 Mtiles, 4 Ntiles, 32 Kchunks of 256 rows), block 256
__device__ __forceinline__ void t3_load(unsigned aB, unsigned bB,
                                        const float* U, const float* X,
                                        int st, int kt, int zb, int m0, int n0, int tid) {
#pragma unroll
    for (int l = 0; l < 2; l++) {
        int c = tid + 256 * l;
        int r = c >> 5;
        int col = (c & 31) * 4;
        int nb = zb + kt * 16 + r;
        int acol = m0 + col;
        int av = (KT - acol) * 4; av = av < 0 ? 0 : (av > 16 ? 16 : av);
        cpa16(aB + (unsigned)(st * 16 * P132 + r * P132 + col) * 4u,
              &U[(size_t)nb * KT + acol], av);
        cpa16(bB + (unsigned)(st * 16 * P132 + r * P132 + col) * 4u,
              &X[(size_t)nb * CINC + n0 + col], 16);
    }
}

__global__ void __launch_bounds__(256, 2) k_gemmT3(const float* __restrict__ U,
                                                   const float* __restrict__ X) {
    extern __shared__ float smf[];
    float* As = smf;                      // [3][16][P132]
    float* Bs = smf + 3 * 16 * P132;
    unsigned aB = smem_u32(As), bB = smem_u32(Bs);

    int m0 = blockIdx.x * 128;
    int n0 = blockIdx.y * 128;
    int zb = blockIdx.z * 256;
    int tid = threadIdx.x;
    int w = tid >> 5, lane = tid & 31, g = lane >> 2, t4 = lane & 3;
    int wm = w & 1, wn = w >> 1;
    float C[4][4][4];
#pragma unroll
    for (int i = 0; i < 4; i++)
#pragma unroll
        for (int j = 0; j < 4; j++) { C[i][j][0] = C[i][j][1] = C[i][j][2] = C[i][j][3] = 0.f; }

    t3_load(aB, bB, U, X, 0, 0, zb, m0, n0, tid);
    CP_COMMIT();
    t3_load(aB, bB, U, X, 1, 1, zb, m0, n0, tid);
    CP_COMMIT();

    for (int kt = 0; kt < 16; kt++) {
        if (kt < 15) { CP_WAIT1(); } else { CP_WAIT0(); }
        __syncthreads();
        int st = kt % 3;
        const float* AsP = As + st * 16 * P132;
        const float* BsP = Bs + st * 16 * P132;
        unsigned bh[4][2], bl[4][2];
#pragma unroll
        for (int ni = 0; ni < 4; ni++) {
            int cn = wn * 32 + ni * 8 + g;
            bsplit(bh[ni][0], bl[ni][0], BsP[(2*t4)   * P132 + cn], BsP[(2*t4+1) * P132 + cn]);
            bsplit(bh[ni][1], bl[ni][1], BsP[(2*t4+8) * P132 + cn], BsP[(2*t4+9) * P132 + cn]);
        }
#pragma unroll
        for (int mi = 0; mi < 4; mi++) {
            int rm = wm * 64 + mi * 16 + g;
            unsigned ah[4], al[4];
            bsplit(ah[0], al[0], AsP[(2*t4)   * P132 + rm],     AsP[(2*t4+1) * P132 + rm]);
            bsplit(ah[1], al[1], AsP[(2*t4)   * P132 + rm + 8], AsP[(2*t4+1) * P132 + rm + 8]);
            bsplit(ah[2], al[2], AsP[(2*t4+8) * P132 + rm],     AsP[(2*t4+9) * P132 + rm]);
            bsplit(ah[3], al[3], AsP[(2*t4+8) * P132 + rm + 8], AsP[(2*t4+9) * P132 + rm + 8]);
#pragma unroll
            for (int ni = 0; ni < 4; ni++) {
                mma_bf16(C[mi][ni], ah, bl[ni]);
                mma_bf16(C[mi][ni], al, bh[ni]);
                mma_bf16(C[mi][ni], ah, bh[ni]);
            }
        }
        if (kt + 2 < 16) {
            t3_load(aB, bB, U, X, (kt + 2) % 3, kt + 2, zb, m0, n0, tid);
            CP_COMMIT();
        }
    }
#pragma unroll
    for (int mi = 0; mi < 4; mi++) {
        int r = m0 + wm * 64 + mi * 16 + g;
#pragma unroll
        for (int ni = 0; ni < 4; ni++) {
            int c = n0 + wn * 32 + ni * 8 + 2 * t4;
            if (r < KT) {
                atomicAdd(&d_Tm[r * CINC + c],     C[mi][ni][0]);
                atomicAdd(&d_Tm[r * CINC + c + 1], C[mi][ni][1]);
            }
            if (r + 8 < KT) {
                atomicAdd(&d_Tm[(r + 8) * CINC + c],     C[mi][ni][2]);
                atomicAdd(&d_Tm[(r + 8) * CINC + c + 1], C[mi][ni][3]);
            }
        }
    }
}

// ============ P = T @ Ww : atomic-free, broadcast-smem, 25 blocks ============
__global__ void __launch_bounds__(256) k_gemmP(const float* __restrict__ Ww) {
    __shared__ float As[8 * CINC];   // 16 KB
    int m0 = blockIdx.x * 8;
    int tid = threadIdx.x;
#pragma unroll
    for (int l = 0; l < 16; l++) {
        int idx = tid + 256 * l;
        As[idx] = d_Tm[(m0 + (idx >> 9)) * CINC + (idx & 511)];
    }
    __syncthreads();
    float acc[8] = {};
#pragma unroll 4
    for (int k = 0; k < CINC; k++) {
        float wv = Ww[k * HIDC + tid];
#pragma unroll
        for (int i = 0; i < 8; i++)
            acc[i] = fmaf(As[i * CINC + k], wv, acc[i]);
    }
#pragma unroll
    for (int i = 0; i < 8; i++)
        d_P[(m0 + i) * HIDC + tid] = acc[i];
}

// ============ hidden = (U*s)@P + Wb : bf16-split3, 3-stage, gate+BN fused ============
__device__ __forceinline__ void h3_load(unsigned aB, unsigned bB,
                                        const float* U,
                                        int st, int kt, int m0, int n0, int tid) {
    int kbase = kt * 16;
    {
        int r = tid >> 2;
        int kcol = (tid & 3) * 4;
        int kk = kbase + kcol;
        int av = (KT - kk) * 4; av = av < 0 ? 0 : (av > 16 ? 16 : av);
        cpa16(aB + (unsigned)(st * 64 * PKA + r * PKA + kcol) * 4u,
              &U[(size_t)(m0 + r) * KT + kk], av);
    }
#pragma unroll
    for (int l = 0; l < 2; l++) {
        int c = tid + 256 * l;
        int r = c >> 5;
        int col = (c & 31) * 4;
        int kk = kbase + r;
        int bv = (kk < KT) ? 16 : 0;
        cpa16(bB + (unsigned)(st * 16 * P132 + r * P132 + col) * 4u,
              &d_P[(size_t)kk * HIDC + n0 + col], bv);
    }
}

__global__ void __launch_bounds__(256, 2) k_gemmH3(const float* __restrict__ U,
                                                   const float* __restrict__ La,
                                                   const float* __restrict__ gW1, const float* __restrict__ gb1,
                                                   const float* __restrict__ gW2, const float* __restrict__ gb2,
                                                   const float* __restrict__ Wb,
                                                   float* __restrict__ hid) {
    extern __shared__ float smf[];
    float* As = smf;                      // [3][64][PKA]
    float* Bs = smf + 3 * 64 * PKA;       // [3][16][P132]
    unsigned aB = smem_u32(As), bB = smem_u32(Bs);
    __shared__ float sS[128], sQ[128];
    __shared__ float s_sm[224];
    __shared__ float stats[EE], gsh[EE];

    int m0 = blockIdx.x * 64;
    int n0 = blockIdx.y * 128;
    int tid = threadIdx.x;
    int w = tid >> 5, lane = tid & 31, g = lane >> 2, t4 = lane & 3;
    int wm = w & 1, wn = w >> 1;

    if (tid < 128) { sS[tid] = 0.f; sQ[tid] = 0.f; }
    if (tid < 224) s_sm[tid] = 0.f;
    if (tid < EE) {
        float s = 0.f;
        for (int i = 0; i < 40; i++) s += La[tid * 40 + i];
        stats[tid] = s * (1.f / 40.f);
    }
    __syncthreads();
    if (tid == 0) {
        float h[EE], g2[EE];
        for (int j = 0; j < EE; j++) {
            float a = gb1[j];
            for (int i = 0; i < EE; i++) a = fmaf(stats[i], gW1[i * EE + j], a);
            h[j] = fmaxf(a, 0.f);
        }
        for (int j = 0; j < EE; j++) {
            float a = gb2[j];
            for (int i = 0; i < EE; i++) a = fmaf(h[i], gW2[i * EE + j], a);
            g2[j] = a;
        }
        float m = g2[0];
        for (int j = 1; j < EE; j++) m = fmaxf(m, g2[j]);
        float se = 0.f;
        for (int j = 0; j < EE; j++) { g2[j] = expf(g2[j] - m); se += g2[j]; }
        for (int j = 0; j < EE; j++) gsh[j] = g2[j] / se;
    }
    __syncthreads();
    if (tid < KT) s_sm[tid] = gsh[tid / 40] * d_Vsum[tid] * (1.f / (float)NT);
    __syncthreads();

    float C[2][4][4];
#pragma unroll
    for (int i = 0; i < 2; i++)
#pragma unroll
        for (int j = 0; j < 4; j++) { C[i][j][0] = C[i][j][1] = C[i][j][2] = C[i][j][3] = 0.f; }

    h3_load(aB, bB, U, 0, 0, m0, n0, tid);
    CP_COMMIT();
    h3_load(aB, bB, U, 1, 1, m0, n0, tid);
    CP_COMMIT();

    for (int kt = 0; kt < 13; kt++) {
        if (kt < 12) { CP_WAIT1(); } else { CP_WAIT0(); }
        __syncthreads();
        int st = kt % 3;
        const float* AsP = As + st * 64 * PKA;
        const float* BsP = Bs + st * 16 * P132;
        int kb = kt * 16;
        float sv0 = s_sm[kb + 2*t4],     sv1 = s_sm[kb + 2*t4 + 1];
        float sv2 = s_sm[kb + 2*t4 + 8], sv3 = s_sm[kb + 2*t4 + 9];
        unsigned bh[4][2], bl[4][2];
#pragma unroll
        for (int ni = 0; ni < 4; ni++) {
            int cn = wn * 32 + ni * 8 + g;
            bsplit(bh[ni][0], bl[ni][0], BsP[(2*t4)   * P132 + cn], BsP[(2*t4+1) * P132 + cn]);
            bsplit(bh[ni][1], bl[ni][1], BsP[(2*t4+8) * P132 + cn], BsP[(2*t4+9) * P132 + cn]);
        }
#pragma unroll
        for (int mi = 0; mi < 2; mi++) {
            int rm = wm * 32 + mi * 16 + g;
            unsigned ah[4], al[4];
            float2 p0 = *(const float2*)&AsP[rm       * PKA + 2*t4];
            float2 p1 = *(const float2*)&AsP[(rm + 8) * PKA + 2*t4];
            float2 p2 = *(const float2*)&AsP[rm       * PKA + 2*t4 + 8];
            float2 p3 = *(const float2*)&AsP[(rm + 8) * PKA + 2*t4 + 8];
            bsplit(ah[0], al[0], p0.x * sv0, p0.y * sv1);
            bsplit(ah[1], al[1], p1.x * sv0, p1.y * sv1);
            bsplit(ah[2], al[2], p2.x * sv2, p2.y * sv3);
            bsplit(ah[3], al[3], p3.x * sv2, p3.y * sv3);
#pragma unroll
            for (int ni = 0; ni < 4; ni++) {
                mma_bf16(C[mi][ni], ah, bl[ni]);
                mma_bf16(C[mi][ni], al, bh[ni]);
                mma_bf16(C[mi][ni], ah, bh[ni]);
            }
        }
        if (kt + 2 < 13) {
            h3_load(aB, bB, U, (kt + 2) % 3, kt + 2, m0, n0, tid);
            CP_COMMIT();
        }
    }
    float ls[8] = {}, lq[8] = {};
#pragma unroll
    for (int mi = 0; mi < 2; mi++) {
        int r = m0 + wm * 32 + mi * 16 + g;
#pragma unroll
        for (int ni = 0; ni < 4; ni++) {
            int c = n0 + wn * 32 + ni * 8 + 2 * t4;
            float b0 = Wb[c], b1 = Wb[c + 1];
            float v0 = C[mi][ni][0] + b0, v1 = C[mi][ni][1] + b1;
            float v2 = C[mi][ni][2] + b0, v3 = C[mi][ni][3] + b1;
            hid[r * HIDC + c] = v0;
            hid[r * HIDC + c + 1] = v1;
            hid[(r + 8) * HIDC + c] = v2;
            hid[(r + 8) * HIDC + c + 1] = v3;
            ls[ni * 2]     += v0 + v2;  lq[ni * 2]     += v0 * v0 + v2 * v2;
            ls[ni * 2 + 1] += v1 + v3;  lq[ni * 2 + 1] += v1 * v1 + v3 * v3;
        }
    }
#pragma unroll
    for (int j = 0; j < 8; j++) {
        float a = ls[j], q = lq[j];
        a += __shfl_xor_sync(0xffffffffu, a, 4);
        a += __shfl_xor_sync(0xffffffffu, a, 8);
        a += __shfl_xor_sync(0xffffffffu, a, 16);
        q += __shfl_xor_sync(0xffffffffu, q, 4);
        q += __shfl_xor_sync(0xffffffffu, q, 8);
        q += __shfl_xor_sync(0xffffffffu, q, 16);
        if (g == 0) {
            int c = wn * 32 + (j >> 1) * 8 + 2 * t4 + (j & 1);
            atomicAdd(&sS[c], a);
            atomicAdd(&sQ[c], q);
        }
    }
    __syncthreads();
    if (tid < 128) {
        atomicAdd(&d_colsum[n0 + tid], sS[tid]);
        atomicAdd(&d_colsq[n0 + tid], sQ[tid]);
    }
}

// ---------------- head: BN-finalize fused, 32 rows/block, Mw in smem ----------------
#define HROWS 32
__global__ void __launch_bounds__(256) k_head(const float* __restrict__ hid,
                       const float* __restrict__ gamma, const float* __restrict__ beta,
                       const float* __restrict__ Mw, const float* __restrict__ Mb,
                       float* __restrict__ out) {
    __shared__ float hs[HROWS][HIDC + 4];
    __shared__ float Ms[HIDC * COUTC];
    __shared__ float lg[HROWS][COUTC];
    __shared__ float mu_s[HIDC], rs_s[HIDC];
    int tid = threadIdx.x;
    int n0 = blockIdx.x * HROWS;

    {
        float m = d_colsum[tid] * (1.f / (float)NT);
        float var = d_colsq[tid] * (1.f / (float)NT) - m * m;
        mu_s[tid] = m;
        rs_s[tid] = rsqrtf(var + 1e-5f);
    }
    for (int i = tid; i < HIDC * COUTC; i += 256) Ms[i] = Mw[i];
    __syncthreads();
    for (int i = tid; i < HROWS * HIDC; i += 256) {
        int r = i >> 8, c = i & 255;
        float v = hid[(n0 + r) * HIDC + c];
        v = fmaf((v - mu_s[c]) * rs_s[c], gamma[c], beta[c]);
        hs[r][c] = fmaxf(v, 0.f);
    }
    __syncthreads();

#pragma unroll
    for (int l = 0; l < 5; l++) {
        int idx = tid + 256 * l;
        int r = idx / COUTC, j = idx % COUTC;
        float a = Mb[j];
#pragma unroll 8
        for (int c = 0; c < HIDC; c++) a = fmaf(hs[r][c], Ms[c * COUTC + j], a);
        lg[r][j] = a;
    }
    __syncthreads();

    int w = tid >> 5, lane = tid & 31;
#pragma unroll
    for (int rr = 0; rr < 4; rr++) {
        int r = w * 4 + rr;
        float v0 = (lane < COUTC) ? lg[r][lane] : -1e30f;
        float v1 = (lane + 32 < COUTC) ? lg[r][lane + 32] : -1e30f;
        float m = fmaxf(v0, v1);
#pragma unroll
        for (int off = 16; off; off >>= 1) m = fmaxf(m, __shfl_xor_sync(0xffffffffu, m, off));
        float se = 0.f;
        if (lane < COUTC) se += expf(v0 - m);
        if (lane + 32 < COUTC) se += expf(v1 - m);
#pragma unroll
        for (int off = 16; off; off >>= 1) se += __shfl_xor_sync(0xffffffffu, se, off);
        float lse = m + logf(se);
        if (lane < COUTC) out[(n0 + r) * COUTC + lane] = v0 - lse;
        if (lane + 32 < COUTC) out[(n0 + r) * COUTC + lane + 32] = v1 - lse;
    }
}

// ---------------- launch ----------------
extern "C" void kernel_launch(void* const* d_in, const int* in_sizes, int n_in,
                              void* d_out, int out_size) {
    const float* X     = (const float*)d_in[0];
    const float* La    = (const float*)d_in[1];
    const float* U     = (const float*)d_in[2];
    const float* eW1   = (const float*)d_in[3];
    const float* eb1   = (const float*)d_in[4];
    const float* eW2   = (const float*)d_in[5];
    const float* eb2   = (const float*)d_in[6];
    const float* eW3   = (const float*)d_in[7];
    const float* eb3   = (const float*)d_in[8];
    const float* gW1   = (const float*)d_in[9];
    const float* gb1   = (const float*)d_in[10];
    const float* gW2   = (const float*)d_in[11];
    const float* gb2   = (const float*)d_in[12];
    const float* Ww    = (const float*)d_in[13];
    const float* Wb    = (const float*)d_in[14];
    const float* gamma = (const float*)d_in[15];
    const float* beta  = (const float*)d_in[16];
    const float* Mw    = (const float*)d_in[17];
    const float* Mb    = (const float*)d_in[18];

    float* out_logits = (float*)d_out;
    float* out_hidden = (float*)d_out + (size_t)NT * COUTC;

    const int SMEM_T3 = 3 * 16 * P132 * 2 * 4;              // 50688 B
    const int SMEM_H3 = (3 * 64 * PKA + 3 * 16 * P132) * 4; // 40704 B
    cudaFuncSetAttribute(k_gemmT3, cudaFuncAttributeMaxDynamicSharedMemorySize, SMEM_T3);
    cudaFuncSetAttribute(k_gemmH3, cudaFuncAttributeMaxDynamicSharedMemorySize, SMEM_H3);

    k_table<<<dim3(TGRID / 128, EE), 128>>>(eW1, eb1, eW2, eb2, eW3, eb3);
    k_reduceV<<<NT / 64, 256>>>(U);
    k_gemmT3<<<dim3(2, 4, 32), 256, SMEM_T3>>>(U, X);
    k_gemmP<<<25, 256>>>(Ww);
    k_gemmH3<<<dim3(128, 2), 256, SMEM_H3>>>(U, La, gW1, gb1, gW2, gb2, Wb, out_hidden);
    k_head<<<NT / HROWS, 256>>>(out_hidden, gamma, beta, Mw, Mb, out_logits);
}

// round 12
// speedup vs baseline: 1.7950x; 1.7950x over previous
#include <cuda_runtime.h>

#define NT    8192
#define KT    200
#define CINC  512
#define HIDC  256
#define COUTC 40
#define EE    5
#define MHD   64
#define TGRID 4096
#define TBL_LO (-8.0f)
#define TBL_HI ( 8.0f)
#define P132  132
#define PKA   20

// ---------------- scratch ----------------
__device__ float d_ftable[EE * TGRID];
__device__ float d_Vsum[KT];
__device__ float d_Tm[KT * CINC];       // T = U^T X   [200 x 512]
__device__ float d_P[KT * HIDC];        // P = T @ Ww  [200 x 256]
__device__ float d_colsum[HIDC], d_colsq[HIDC];

// bf16 split-2: (v0,v1) -> hi bf16x2 + lo bf16x2 (lo = residual); v0 in lo16, v1 in hi16
__device__ __forceinline__ void bsplit(unsigned& hi, unsigned& lo, float v0, float v1) {
    unsigned h;
    asm("cvt.rn.bf16x2.f32 %0, %1, %2;" : "=r"(h) : "f"(v1), "f"(v0));
    float r0 = v0 - __uint_as_float(h << 16);
    float r1 = v1 - __uint_as_float(h & 0xffff0000u);
    unsigned l;
    asm("cvt.rn.bf16x2.f32 %0, %1, %2;" : "=r"(l) : "f"(r1), "f"(r0));
    hi = h; lo = l;
}

__device__ __forceinline__ void mma_bf16(float* c, const unsigned* a, const unsigned* b) {
    asm volatile(
        "mma.sync.aligned.m16n8k16.row.col.f32.bf16.bf16.f32 "
        "{%0,%1,%2,%3},{%4,%5,%6,%7},{%8,%9},{%0,%1,%2,%3};"
        : "+f"(c[0]), "+f"(c[1]), "+f"(c[2]), "+f"(c[3])
        : "r"(a[0]), "r"(a[1]), "r"(a[2]), "r"(a[3]), "r"(b[0]), "r"(b[1]));
}

__device__ __forceinline__ unsigned smem_u32(const void* p) {
    return (unsigned)__cvta_generic_to_shared(p);
}
__device__ __forceinline__ void cpa16(unsigned dst, const void* src, int nbytes) {
    asm volatile("cp.async.cg.shared.global [%0], [%1], 16, %2;\n"
                 :: "r"(dst), "l"(src), "r"(nbytes));
}
#define CP_COMMIT() asm volatile("cp.async.commit_group;\n" ::: "memory")
#define CP_WAIT1()  asm volatile("cp.async.wait_group 1;\n" ::: "memory")
#define CP_WAIT0()  asm volatile("cp.async.wait_group 0;\n" ::: "memory")

// ---------------- tables (+ fused zeroing) ----------------
__global__ void k_table(const float* __restrict__ eW1, const float* __restrict__ eb1,
                        const float* __restrict__ eW2, const float* __restrict__ eb2,
                        const float* __restrict__ eW3, const float* __restrict__ eb3) {
    int gid = (blockIdx.y * gridDim.x + blockIdx.x) * blockDim.x + threadIdx.x;
    int nthr = gridDim.x * gridDim.y * blockDim.x;
    for (int i = gid; i < KT * CINC; i += nthr) d_Tm[i] = 0.f;
    for (int i = gid; i < KT * HIDC; i += nthr) d_P[i] = 0.f;
    if (gid < KT) d_Vsum[gid] = 0.f;
    if (gid < HIDC) { d_colsum[gid] = 0.f; d_colsq[gid] = 0.f; }

    int e = blockIdx.y;
    __shared__ float W2s[MHD * MHD];
    __shared__ float W1s[MHD], b1s[MHD], b2s[MHD], W3s[MHD];
    for (int i = threadIdx.x; i < MHD * MHD; i += blockDim.x) W2s[i] = eW2[e * MHD * MHD + i];
    if (threadIdx.x < MHD) {
        W1s[threadIdx.x] = eW1[e * MHD + threadIdx.x];
        b1s[threadIdx.x] = eb1[e * MHD + threadIdx.x];
        b2s[threadIdx.x] = eb2[e * MHD + threadIdx.x];
        W3s[threadIdx.x] = eW3[e * MHD + threadIdx.x];
    }
    __syncthreads();

    int t = blockIdx.x * blockDim.x + threadIdx.x;
    float x = TBL_LO + (TBL_HI - TBL_LO) * ((float)t / (float)(TGRID - 1));

    float h1[MHD];
#pragma unroll
    for (int h = 0; h < MHD; h++) h1[h] = fmaxf(fmaf(x, W1s[h], b1s[h]), 0.f);

    float v = eb3[e];
    for (int j = 0; j < MHD; j += 4) {
        float a0 = b2s[j], a1 = b2s[j + 1], a2 = b2s[j + 2], a3 = b2s[j + 3];
#pragma unroll
        for (int h = 0; h < MHD; h++) {
            float hv = h1[h];
            float4 w = *(const float4*)&W2s[h * MHD + j];
            a0 = fmaf(hv, w.x, a0);
            a1 = fmaf(hv, w.y, a1);
            a2 = fmaf(hv, w.z, a2);
            a3 = fmaf(hv, w.w, a3);
        }
        v = fmaf(fmaxf(a0, 0.f), W3s[j],     v);
        v = fmaf(fmaxf(a1, 0.f), W3s[j + 1], v);
        v = fmaf(fmaxf(a2, 0.f), W3s[j + 2], v);
        v = fmaf(fmaxf(a3, 0.f), W3s[j + 3], v);
    }
    d_ftable[e * TGRID + t] = v;
}

// ---------------- Vsum[col] = sum_n lerp(f_e, U[n,col]) ----------------
__global__ void k_reduceV(const float* __restrict__ U) {
    int col = threadIdx.x;
    if (col >= KT) return;
    int e = col / 40;
    const float* tbl = d_ftable + e * TGRID;
    const float scale = (float)(TGRID - 1) / (TBL_HI - TBL_LO);
    int n0 = blockIdx.x * 64;

    float sum = 0.f;
    for (int n = n0; n < n0 + 64; n++) {
        float u  = U[n * KT + col];
        float xi = (u - TBL_LO) * scale;
        xi = fminf(fmaxf(xi, 0.f), (float)(TGRID - 2) + 0.9999f);
        int   i  = (int)xi;
        float fr = xi - (float)i;
        float a = tbl[i], b = tbl[i + 1];
        sum += fmaf(fr, b - a, a);
    }
    atomicAdd(&d_Vsum[col], sum);
}

// ============ T = U^T @ X : bf16-split3 m16n8k16, 2-stage ping-pong (R8) ============
// grid (2 Mtiles, 4 Ntiles, 32 Kchunks of 256 rows), block 256
__device__ __forceinline__ void t3_load(unsigned aB, unsigned bB,
                                        const float* U, const float* X,
                                        int st, int kt, int zb, int m0, int n0, int tid) {
#pragma unroll
    for (int l = 0; l < 2; l++) {
        int c = tid + 256 * l;
        int r = c >> 5;
        int col = (c & 31) * 4;
        int nb = zb + kt * 16 + r;
        int acol = m0 + col;
        int av = (KT - acol) * 4; av = av < 0 ? 0 : (av > 16 ? 16 : av);
        cpa16(aB + (unsigned)(st * 16 * P132 + r * P132 + col) * 4u,
              &U[(size_t)nb * KT + acol], av);
        cpa16(bB + (unsigned)(st * 16 * P132 + r * P132 + col) * 4u,
              &X[(size_t)nb * CINC + n0 + col], 16);
    }
}

__global__ void __launch_bounds__(256, 2) k_gemmT3(const float* __restrict__ U,
                                                   const float* __restrict__ X) {
    extern __shared__ float smf[];
    float* As = smf;                      // [2][16][P132]
    float* Bs = smf + 2 * 16 * P132;
    unsigned aB = smem_u32(As), bB = smem_u32(Bs);

    int m0 = blockIdx.x * 128;
    int n0 = blockIdx.y * 128;
    int zb = blockIdx.z * 256;
    int tid = threadIdx.x;
    int w = tid >> 5, lane = tid & 31, g = lane >> 2, t4 = lane & 3;
    int wm = w & 1, wn = w >> 1;
    float C[4][4][4];
#pragma unroll
    for (int i = 0; i < 4; i++)
#pragma unroll
        for (int j = 0; j < 4; j++) { C[i][j][0] = C[i][j][1] = C[i][j][2] = C[i][j][3] = 0.f; }

    t3_load(aB, bB, U, X, 0, 0, zb, m0, n0, tid);
    CP_COMMIT();

    for (int kt = 0; kt < 16; kt++) {
        if (kt < 15) {
            t3_load(aB, bB, U, X, (kt + 1) & 1, kt + 1, zb, m0, n0, tid);
            CP_COMMIT();
            CP_WAIT1();
        } else {
            CP_WAIT0();
        }
        __syncthreads();
        const float* AsP = As + (kt & 1) * 16 * P132;
        const float* BsP = Bs + (kt & 1) * 16 * P132;
        unsigned bh[4][2], bl[4][2];
#pragma unroll
        for (int ni = 0; ni < 4; ni++) {
            int cn = wn * 32 + ni * 8 + g;
            bsplit(bh[ni][0], bl[ni][0], BsP[(2*t4)   * P132 + cn], BsP[(2*t4+1) * P132 + cn]);
            bsplit(bh[ni][1], bl[ni][1], BsP[(2*t4+8) * P132 + cn], BsP[(2*t4+9) * P132 + cn]);
        }
#pragma unroll
        for (int mi = 0; mi < 4; mi++) {
            int rm = wm * 64 + mi * 16 + g;
            unsigned ah[4], al[4];
            bsplit(ah[0], al[0], AsP[(2*t4)   * P132 + rm],     AsP[(2*t4+1) * P132 + rm]);
            bsplit(ah[1], al[1], AsP[(2*t4)   * P132 + rm + 8], AsP[(2*t4+1) * P132 + rm + 8]);
            bsplit(ah[2], al[2], AsP[(2*t4+8) * P132 + rm],     AsP[(2*t4+9) * P132 + rm]);
            bsplit(ah[3], al[3], AsP[(2*t4+8) * P132 + rm + 8], AsP[(2*t4+9) * P132 + rm + 8]);
#pragma unroll
            for (int ni = 0; ni < 4; ni++) {
                mma_bf16(C[mi][ni], ah, bl[ni]);
                mma_bf16(C[mi][ni], al, bh[ni]);
                mma_bf16(C[mi][ni], ah, bh[ni]);
            }
        }
        __syncthreads();
    }
#pragma unroll
    for (int mi = 0; mi < 4; mi++) {
        int r = m0 + wm * 64 + mi * 16 + g;
#pragma unroll
        for (int ni = 0; ni < 4; ni++) {
            int c = n0 + wn * 32 + ni * 8 + 2 * t4;
            if (r < KT) {
                atomicAdd(&d_Tm[r * CINC + c],     C[mi][ni][0]);
                atomicAdd(&d_Tm[r * CINC + c + 1], C[mi][ni][1]);
            }
            if (r + 8 < KT) {
                atomicAdd(&d_Tm[(r + 8) * CINC + c],     C[mi][ni][2]);
                atomicAdd(&d_Tm[(r + 8) * CINC + c + 1], C[mi][ni][3]);
            }
        }
    }
}

// ============ P = T @ Ww : 64x64 tiles, 4x4 reg, split-K 16 (R10, 8.7us) ============
__global__ void __launch_bounds__(256) k_gemmP(const float* __restrict__ Ww) {
    __shared__ float Ast[16][68];
    __shared__ float Bs[16][68];
    int n0 = blockIdx.x * 64;
    int m0 = blockIdx.y * 64;
    int k0 = blockIdx.z * 32;
    int tid = threadIdx.x;
    int tm = tid >> 4, tc = tid & 15;
    float acc[4][4] = {};

    for (int kc = 0; kc < 32; kc += 16) {
#pragma unroll
        for (int l = 0; l < 4; l++) {
            int idx = tid + 256 * l;
            int r = idx >> 4, kk = idx & 15;
            Ast[kk][r] = (m0 + r < KT) ? d_Tm[(m0 + r) * CINC + k0 + kc + kk] : 0.f;
        }
#pragma unroll
        for (int l = 0; l < 4; l++) {
            int idx = tid + 256 * l;
            int kk = idx >> 6, n = idx & 63;
            Bs[kk][n] = Ww[(k0 + kc + kk) * HIDC + n0 + n];
        }
        __syncthreads();
#pragma unroll
        for (int kk = 0; kk < 16; kk++) {
            float4 av = *(const float4*)&Ast[kk][tm * 4];
            float4 bv = *(const float4*)&Bs[kk][tc * 4];
            float a[4] = {av.x, av.y, av.z, av.w};
            float b[4] = {bv.x, bv.y, bv.z, bv.w};
#pragma unroll
            for (int i = 0; i < 4; i++)
#pragma unroll
                for (int j = 0; j < 4; j++)
                    acc[i][j] = fmaf(a[i], b[j], acc[i][j]);
        }
        __syncthreads();
    }
#pragma unroll
    for (int i = 0; i < 4; i++) {
        int r = m0 + tm * 4 + i;
        if (r < KT)
#pragma unroll
            for (int j = 0; j < 4; j++)
                atomicAdd(&d_P[r * HIDC + n0 + tc * 4 + j], acc[i][j]);
    }
}

// ============ hidden = (U*s)@P + Wb : bf16-split3, 2-stage (R8), gate+BN fused ============
__device__ __forceinline__ void h3_load(unsigned aB, unsigned bB,
                                        const float* U,
                                        int st, int kt, int m0, int n0, int tid) {
    int kbase = kt * 16;
    {
        int r = tid >> 2;
        int kcol = (tid & 3) * 4;
        int kk = kbase + kcol;
        int av = (KT - kk) * 4; av = av < 0 ? 0 : (av > 16 ? 16 : av);
        cpa16(aB + (unsigned)(st * 64 * PKA + r * PKA + kcol) * 4u,
              &U[(size_t)(m0 + r) * KT + kk], av);
    }
#pragma unroll
    for (int l = 0; l < 2; l++) {
        int c = tid + 256 * l;
        int r = c >> 5;
        int col = (c & 31) * 4;
        int kk = kbase + r;
        int bv = (kk < KT) ? 16 : 0;
        cpa16(bB + (unsigned)(st * 16 * P132 + r * P132 + col) * 4u,
              &d_P[(size_t)kk * HIDC + n0 + col], bv);
    }
}

__global__ void __launch_bounds__(256, 2) k_gemmH3(const float* __restrict__ U,
                                                   const float* __restrict__ La,
                                                   const float* __restrict__ gW1, const float* __restrict__ gb1,
                                                   const float* __restrict__ gW2, const float* __restrict__ gb2,
                                                   const float* __restrict__ Wb,
                                                   float* __restrict__ hid) {
    extern __shared__ float smf[];
    float* As = smf;                      // [2][64][PKA]
    float* Bs = smf + 2 * 64 * PKA;       // [2][16][P132]
    unsigned aB = smem_u32(As), bB = smem_u32(Bs);
    __shared__ float sS[128], sQ[128];
    __shared__ float s_sm[224];
    __shared__ float stats[EE], gsh[EE];

    int m0 = blockIdx.x * 64;
    int n0 = blockIdx.y * 128;
    int tid = threadIdx.x;
    int w = tid >> 5, lane = tid & 31, g = lane >> 2, t4 = lane & 3;
    int wm = w & 1, wn = w >> 1;

    if (tid < 128) { sS[tid] = 0.f; sQ[tid] = 0.f; }
    if (tid < 224) s_sm[tid] = 0.f;
    if (tid < EE) {
        float s = 0.f;
        for (int i = 0; i < 40; i++) s += La[tid * 40 + i];
        stats[tid] = s * (1.f / 40.f);
    }
    __syncthreads();
    if (tid == 0) {
        float h[EE], g2[EE];
        for (int j = 0; j < EE; j++) {
            float a = gb1[j];
            for (int i = 0; i < EE; i++) a = fmaf(stats[i], gW1[i * EE + j], a);
            h[j] = fmaxf(a, 0.f);
        }
        for (int j = 0; j < EE; j++) {
            float a = gb2[j];
            for (int i = 0; i < EE; i++) a = fmaf(h[i], gW2[i * EE + j], a);
            g2[j] = a;
        }
        float m = g2[0];
        for (int j = 1; j < EE; j++) m = fmaxf(m, g2[j]);
        float se = 0.f;
        for (int j = 0; j < EE; j++) { g2[j] = expf(g2[j] - m); se += g2[j]; }
        for (int j = 0; j < EE; j++) gsh[j] = g2[j] / se;
    }
    __syncthreads();
    if (tid < KT) s_sm[tid] = gsh[tid / 40] * d_Vsum[tid] * (1.f / (float)NT);
    __syncthreads();

    float C[2][4][4];
#pragma unroll
    for (int i = 0; i < 2; i++)
#pragma unroll
        for (int j = 0; j < 4; j++) { C[i][j][0] = C[i][j][1] = C[i][j][2] = C[i][j][3] = 0.f; }

    h3_load(aB, bB, U, 0, 0, m0, n0, tid);
    CP_COMMIT();

    for (int kt = 0; kt < 13; kt++) {
        if (kt < 12) {
            h3_load(aB, bB, U, (kt + 1) & 1, kt + 1, m0, n0, tid);
            CP_COMMIT();
            CP_WAIT1();
        } else {
            CP_WAIT0();
        }
        __syncthreads();
        const float* AsP = As + (kt & 1) * 64 * PKA;
        const float* BsP = Bs + (kt & 1) * 16 * P132;
        int kb = kt * 16;
        float sv0 = s_sm[kb + 2*t4],     sv1 = s_sm[kb + 2*t4 + 1];
        float sv2 = s_sm[kb + 2*t4 + 8], sv3 = s_sm[kb + 2*t4 + 9];
        unsigned bh[4][2], bl[4][2];
#pragma unroll
        for (int ni = 0; ni < 4; ni++) {
            int cn = wn * 32 + ni * 8 + g;
            bsplit(bh[ni][0], bl[ni][0], BsP[(2*t4)   * P132 + cn], BsP[(2*t4+1) * P132 + cn]);
            bsplit(bh[ni][1], bl[ni][1], BsP[(2*t4+8) * P132 + cn], BsP[(2*t4+9) * P132 + cn]);
        }
#pragma unroll
        for (int mi = 0; mi < 2; mi++) {
            int rm = wm * 32 + mi * 16 + g;
            unsigned ah[4], al[4];
            float2 p0 = *(const float2*)&AsP[rm       * PKA + 2*t4];
            float2 p1 = *(const float2*)&AsP[(rm + 8) * PKA + 2*t4];
            float2 p2 = *(const float2*)&AsP[rm       * PKA + 2*t4 + 8];
            float2 p3 = *(const float2*)&AsP[(rm + 8) * PKA + 2*t4 + 8];
            bsplit(ah[0], al[0], p0.x * sv0, p0.y * sv1);
            bsplit(ah[1], al[1], p1.x * sv0, p1.y * sv1);
            bsplit(ah[2], al[2], p2.x * sv2, p2.y * sv3);
            bsplit(ah[3], al[3], p3.x * sv2, p3.y * sv3);
#pragma unroll
            for (int ni = 0; ni < 4; ni++) {
                mma_bf16(C[mi][ni], ah, bl[ni]);
                mma_bf16(C[mi][ni], al, bh[ni]);
                mma_bf16(C[mi][ni], ah, bh[ni]);
            }
        }
        __syncthreads();
    }
    float ls[8] = {}, lq[8] = {};
#pragma unroll
    for (int mi = 0; mi < 2; mi++) {
        int r = m0 + wm * 32 + mi * 16 + g;
#pragma unroll
        for (int ni = 0; ni < 4; ni++) {
            int c = n0 + wn * 32 + ni * 8 + 2 * t4;
            float b0 = Wb[c], b1 = Wb[c + 1];
            float v0 = C[mi][ni][0] + b0, v1 = C[mi][ni][1] + b1;
            float v2 = C[mi][ni][2] + b0, v3 = C[mi][ni][3] + b1;
            hid[r * HIDC + c] = v0;
            hid[r * HIDC + c + 1] = v1;
            hid[(r + 8) * HIDC + c] = v2;
            hid[(r + 8) * HIDC + c + 1] = v3;
            ls[ni * 2]     += v0 + v2;  lq[ni * 2]     += v0 * v0 + v2 * v2;
            ls[ni * 2 + 1] += v1 + v3;  lq[ni * 2 + 1] += v1 * v1 + v3 * v3;
        }
    }
#pragma unroll
    for (int j = 0; j < 8; j++) {
        float a = ls[j], q = lq[j];
        a += __shfl_xor_sync(0xffffffffu, a, 4);
        a += __shfl_xor_sync(0xffffffffu, a, 8);
        a += __shfl_xor_sync(0xffffffffu, a, 16);
        q += __shfl_xor_sync(0xffffffffu, q, 4);
        q += __shfl_xor_sync(0xffffffffu, q, 8);
        q += __shfl_xor_sync(0xffffffffu, q, 16);
        if (g == 0) {
            int c = wn * 32 + (j >> 1) * 8 + 2 * t4 + (j & 1);
            atomicAdd(&sS[c], a);
            atomicAdd(&sQ[c], q);
        }
    }
    __syncthreads();
    if (tid < 128) {
        atomicAdd(&d_colsum[n0 + tid], sS[tid]);
        atomicAdd(&d_colsq[n0 + tid], sQ[tid]);
    }
}

// ---------------- head: BN-finalize fused, 32 rows/block, Mw in smem ----------------
#define HROWS 32
__global__ void __launch_bounds__(256) k_head(const float* __restrict__ hid,
                       const float* __restrict__ gamma, const float* __restrict__ beta,
                       const float* __restrict__ Mw, const float* __restrict__ Mb,
                       float* __restrict__ out) {
    __shared__ float hs[HROWS][HIDC + 4];
    __shared__ float Ms[HIDC * COUTC];
    __shared__ float lg[HROWS][COUTC];
    __shared__ float mu_s[HIDC], rs_s[HIDC];
    int tid = threadIdx.x;
    int n0 = blockIdx.x * HROWS;

    {
        float m = d_colsum[tid] * (1.f / (float)NT);
        float var = d_colsq[tid] * (1.f / (float)NT) - m * m;
        mu_s[tid] = m;
        rs_s[tid] = rsqrtf(var + 1e-5f);
    }
    for (int i = tid; i < HIDC * COUTC; i += 256) Ms[i] = Mw[i];
    __syncthreads();
    for (int i = tid; i < HROWS * HIDC; i += 256) {
        int r = i >> 8, c = i & 255;
        float v = hid[(n0 + r) * HIDC + c];
        v = fmaf((v - mu_s[c]) * rs_s[c], gamma[c], beta[c]);
        hs[r][c] = fmaxf(v, 0.f);
    }
    __syncthreads();

#pragma unroll
    for (int l = 0; l < 5; l++) {
        int idx = tid + 256 * l;
        int r = idx / COUTC, j = idx % COUTC;
        float a = Mb[j];
#pragma unroll 8
        for (int c = 0; c < HIDC; c++) a = fmaf(hs[r][c], Ms[c * COUTC + j], a);
        lg[r][j] = a;
    }
    __syncthreads();

    int w = tid >> 5, lane = tid & 31;
#pragma unroll
    for (int rr = 0; rr < 4; rr++) {
        int r = w * 4 + rr;
        float v0 = (lane < COUTC) ? lg[r][lane] : -1e30f;
        float v1 = (lane + 32 < COUTC) ? lg[r][lane + 32] : -1e30f;
        float m = fmaxf(v0, v1);
#pragma unroll
        for (int off = 16; off; off >>= 1) m = fmaxf(m, __shfl_xor_sync(0xffffffffu, m, off));
        float se = 0.f;
        if (lane < COUTC) se += expf(v0 - m);
        if (lane + 32 < COUTC) se += expf(v1 - m);
#pragma unroll
        for (int off = 16; off; off >>= 1) se += __shfl_xor_sync(0xffffffffu, se, off);
        float lse = m + logf(se);
        if (lane < COUTC) out[(n0 + r) * COUTC + lane] = v0 - lse;
        if (lane + 32 < COUTC) out[(n0 + r) * COUTC + lane + 32] = v1 - lse;
    }
}

// ---------------- launch ----------------
extern "C" void kernel_launch(void* const* d_in, const int* in_sizes, int n_in,
                              void* d_out, int out_size) {
    const float* X     = (const float*)d_in[0];
    const float* La    = (const float*)d_in[1];
    const float* U     = (const float*)d_in[2];
    const float* eW1   = (const float*)d_in[3];
    const float* eb1   = (const float*)d_in[4];
    const float* eW2   = (const float*)d_in[5];
    const float* eb2   = (const float*)d_in[6];
    const float* eW3   = (const float*)d_in[7];
    const float* eb3   = (const float*)d_in[8];
    const float* gW1   = (const float*)d_in[9];
    const float* gb1   = (const float*)d_in[10];
    const float* gW2   = (const float*)d_in[11];
    const float* gb2   = (const float*)d_in[12];
    const float* Ww    = (const float*)d_in[13];
    const float* Wb    = (const float*)d_in[14];
    const float* gamma = (const float*)d_in[15];
    const float* beta  = (const float*)d_in[16];
    const float* Mw    = (const float*)d_in[17];
    const float* Mb    = (const float*)d_in[18];

    float* out_logits = (float*)d_out;
    float* out_hidden = (float*)d_out + (size_t)NT * COUTC;

    const int SMEM_T3 = 2 * 16 * P132 * 2 * 4;              // 33792 B
    const int SMEM_H3 = (2 * 64 * PKA + 2 * 16 * P132) * 4; // 27136 B
    cudaFuncSetAttribute(k_gemmT3, cudaFuncAttributeMaxDynamicSharedMemorySize, SMEM_T3);
    cudaFuncSetAttribute(k_gemmH3, cudaFuncAttributeMaxDynamicSharedMemorySize, SMEM_H3);

    k_table<<<dim3(TGRID / 128, EE), 128>>>(eW1, eb1, eW2, eb2, eW3, eb3);
    k_reduceV<<<NT / 64, 256>>>(U);
    k_gemmT3<<<dim3(2, 4, 32), 256, SMEM_T3>>>(U, X);
    k_gemmP<<<dim3(4, 4, 16), 256>>>(Ww);
    k_gemmH3<<<dim3(128, 2), 256, SMEM_H3>>>(U, La, gW1, gb1, gW2, gb2, Wb, out_hidden);
    k_head<<<NT / HROWS, 256>>>(out_hidden, gamma, beta, Mw, Mb, out_logits);
}

// round 13
// speedup vs baseline: 1.9041x; 1.0608x over previous
#include <cuda_runtime.h>

#define NT    8192
#define KT    200
#define CINC  512
#define HIDC  256
#define COUTC 40
#define EE    5
#define MHD   64
#define TGRID 2048
#define TBL_LO (-8.0f)
#define TBL_HI ( 8.0f)
#define P132  132
#define PKA   20

// ---------------- scratch ----------------
__device__ float d_ftable[EE * TGRID];
__device__ float d_Vsum[KT];
__device__ float d_Tm[KT * CINC];       // T = U^T X   [200 x 512]
__device__ float d_P[KT * HIDC];        // P = T @ Ww  [200 x 256]
__device__ float d_colsum[HIDC], d_colsq[HIDC];

// bf16 split-2: (v0,v1) -> hi bf16x2 + lo bf16x2 (lo = residual); v0 in lo16, v1 in hi16
__device__ __forceinline__ void bsplit(unsigned& hi, unsigned& lo, float v0, float v1) {
    unsigned h;
    asm("cvt.rn.bf16x2.f32 %0, %1, %2;" : "=r"(h) : "f"(v1), "f"(v0));
    float r0 = v0 - __uint_as_float(h << 16);
    float r1 = v1 - __uint_as_float(h & 0xffff0000u);
    unsigned l;
    asm("cvt.rn.bf16x2.f32 %0, %1, %2;" : "=r"(l) : "f"(r1), "f"(r0));
    hi = h; lo = l;
}

__device__ __forceinline__ void mma_bf16(float* c, const unsigned* a, const unsigned* b) {
    asm volatile(
        "mma.sync.aligned.m16n8k16.row.col.f32.bf16.bf16.f32 "
        "{%0,%1,%2,%3},{%4,%5,%6,%7},{%8,%9},{%0,%1,%2,%3};"
        : "+f"(c[0]), "+f"(c[1]), "+f"(c[2]), "+f"(c[3])
        : "r"(a[0]), "r"(a[1]), "r"(a[2]), "r"(a[3]), "r"(b[0]), "r"(b[1]));
}

__device__ __forceinline__ unsigned smem_u32(const void* p) {
    return (unsigned)__cvta_generic_to_shared(p);
}
__device__ __forceinline__ void cpa16(unsigned dst, const void* src, int nbytes) {
    asm volatile("cp.async.cg.shared.global [%0], [%1], 16, %2;\n"
                 :: "r"(dst), "l"(src), "r"(nbytes));
}
#define CP_COMMIT() asm volatile("cp.async.commit_group;\n" ::: "memory")
#define CP_WAIT1()  asm volatile("cp.async.wait_group 1;\n" ::: "memory")
#define CP_WAIT0()  asm volatile("cp.async.wait_group 0;\n" ::: "memory")

// ---------------- tables (+ fused zeroing) ----------------
__global__ void k_table(const float* __restrict__ eW1, const float* __restrict__ eb1,
                        const float* __restrict__ eW2, const float* __restrict__ eb2,
                        const float* __restrict__ eW3, const float* __restrict__ eb3) {
    int gid = (blockIdx.y * gridDim.x + blockIdx.x) * blockDim.x + threadIdx.x;
    int nthr = gridDim.x * gridDim.y * blockDim.x;
    for (int i = gid; i < KT * CINC; i += nthr) d_Tm[i] = 0.f;
    for (int i = gid; i < KT * HIDC; i += nthr) d_P[i] = 0.f;
    if (gid < KT) d_Vsum[gid] = 0.f;
    if (gid < HIDC) { d_colsum[gid] = 0.f; d_colsq[gid] = 0.f; }

    int e = blockIdx.y;
    __shared__ float W2s[MHD * MHD];
    __shared__ float W1s[MHD], b1s[MHD], b2s[MHD], W3s[MHD];
    for (int i = threadIdx.x; i < MHD * MHD; i += blockDim.x) W2s[i] = eW2[e * MHD * MHD + i];
    if (threadIdx.x < MHD) {
        W1s[threadIdx.x] = eW1[e * MHD + threadIdx.x];
        b1s[threadIdx.x] = eb1[e * MHD + threadIdx.x];
        b2s[threadIdx.x] = eb2[e * MHD + threadIdx.x];
        W3s[threadIdx.x] = eW3[e * MHD + threadIdx.x];
    }
    __syncthreads();

    int t = blockIdx.x * blockDim.x + threadIdx.x;
    float x = TBL_LO + (TBL_HI - TBL_LO) * ((float)t / (float)(TGRID - 1));

    float h1[MHD];
#pragma unroll
    for (int h = 0; h < MHD; h++) h1[h] = fmaxf(fmaf(x, W1s[h], b1s[h]), 0.f);

    float v = eb3[e];
    for (int j = 0; j < MHD; j += 4) {
        float a0 = b2s[j], a1 = b2s[j + 1], a2 = b2s[j + 2], a3 = b2s[j + 3];
#pragma unroll
        for (int h = 0; h < MHD; h++) {
            float hv = h1[h];
            float4 w = *(const float4*)&W2s[h * MHD + j];
            a0 = fmaf(hv, w.x, a0);
            a1 = fmaf(hv, w.y, a1);
            a2 = fmaf(hv, w.z, a2);
            a3 = fmaf(hv, w.w, a3);
        }
        v = fmaf(fmaxf(a0, 0.f), W3s[j],     v);
        v = fmaf(fmaxf(a1, 0.f), W3s[j + 1], v);
        v = fmaf(fmaxf(a2, 0.f), W3s[j + 2], v);
        v = fmaf(fmaxf(a3, 0.f), W3s[j + 3], v);
    }
    d_ftable[e * TGRID + t] = v;
}

// ---------------- Vsum[col] = sum_n lerp(f_e, U[n,col]), 256 blocks ----------------
__global__ void k_reduceV(const float* __restrict__ U) {
    int col = threadIdx.x;
    if (col >= KT) return;
    int e = col / 40;
    const float* tbl = d_ftable + e * TGRID;
    const float scale = (float)(TGRID - 1) / (TBL_HI - TBL_LO);
    int n0 = blockIdx.x * 32;

    float sum = 0.f;
    for (int n = n0; n < n0 + 32; n++) {
        float u  = U[n * KT + col];
        float xi = (u - TBL_LO) * scale;
        xi = fminf(fmaxf(xi, 0.f), (float)(TGRID - 2) + 0.9999f);
        int   i  = (int)xi;
        float fr = xi - (float)i;
        float a = tbl[i], b = tbl[i + 1];
        sum += fmaf(fr, b - a, a);
    }
    atomicAdd(&d_Vsum[col], sum);
}

// ============ T = U^T @ X : bf16-split3 m16n8k16, 2-stage ping-pong (R8 golden) ============
// grid (2 Mtiles, 4 Ntiles, 32 Kchunks of 256 rows), block 256
__device__ __forceinline__ void t3_load(unsigned aB, unsigned bB,
                                        const float* U, const float* X,
                                        int st, int kt, int zb, int m0, int n0, int tid) {
#pragma unroll
    for (int l = 0; l < 2; l++) {
        int c = tid + 256 * l;
        int r = c >> 5;
        int col = (c & 31) * 4;
        int nb = zb + kt * 16 + r;
        int acol = m0 + col;
        int av = (KT - acol) * 4; av = av < 0 ? 0 : (av > 16 ? 16 : av);
        cpa16(aB + (unsigned)(st * 16 * P132 + r * P132 + col) * 4u,
              &U[(size_t)nb * KT + acol], av);
        cpa16(bB + (unsigned)(st * 16 * P132 + r * P132 + col) * 4u,
              &X[(size_t)nb * CINC + n0 + col], 16);
    }
}

__global__ void __launch_bounds__(256, 2) k_gemmT3(const float* __restrict__ U,
                                                   const float* __restrict__ X) {
    extern __shared__ float smf[];
    float* As = smf;                      // [2][16][P132]
    float* Bs = smf + 2 * 16 * P132;
    unsigned aB = smem_u32(As), bB = smem_u32(Bs);

    int m0 = blockIdx.x * 128;
    int n0 = blockIdx.y * 128;
    int zb = blockIdx.z * 256;
    int tid = threadIdx.x;
    int w = tid >> 5, lane = tid & 31, g = lane >> 2, t4 = lane & 3;
    int wm = w & 1, wn = w >> 1;
    float C[4][4][4];
#pragma unroll
    for (int i = 0; i < 4; i++)
#pragma unroll
        for (int j = 0; j < 4; j++) { C[i][j][0] = C[i][j][1] = C[i][j][2] = C[i][j][3] = 0.f; }

    t3_load(aB, bB, U, X, 0, 0, zb, m0, n0, tid);
    CP_COMMIT();

    for (int kt = 0; kt < 16; kt++) {
        if (kt < 15) {
            t3_load(aB, bB, U, X, (kt + 1) & 1, kt + 1, zb, m0, n0, tid);
            CP_COMMIT();
            CP_WAIT1();
        } else {
            CP_WAIT0();
        }
        __syncthreads();
        const float* AsP = As + (kt & 1) * 16 * P132;
        const float* BsP = Bs + (kt & 1) * 16 * P132;
        unsigned bh[4][2], bl[4][2];
#pragma unroll
        for (int ni = 0; ni < 4; ni++) {
            int cn = wn * 32 + ni * 8 + g;
            bsplit(bh[ni][0], bl[ni][0], BsP[(2*t4)   * P132 + cn], BsP[(2*t4+1) * P132 + cn]);
            bsplit(bh[ni][1], bl[ni][1], BsP[(2*t4+8) * P132 + cn], BsP[(2*t4+9) * P132 + cn]);
        }
#pragma unroll
        for (int mi = 0; mi < 4; mi++) {
            int rm = wm * 64 + mi * 16 + g;
            unsigned ah[4], al[4];
            bsplit(ah[0], al[0], AsP[(2*t4)   * P132 + rm],     AsP[(2*t4+1) * P132 + rm]);
            bsplit(ah[1], al[1], AsP[(2*t4)   * P132 + rm + 8], AsP[(2*t4+1) * P132 + rm + 8]);
            bsplit(ah[2], al[2], AsP[(2*t4+8) * P132 + rm],     AsP[(2*t4+9) * P132 + rm]);
            bsplit(ah[3], al[3], AsP[(2*t4+8) * P132 + rm + 8], AsP[(2*t4+9) * P132 + rm + 8]);
#pragma unroll
            for (int ni = 0; ni < 4; ni++) {
                mma_bf16(C[mi][ni], ah, bl[ni]);
                mma_bf16(C[mi][ni], al, bh[ni]);
                mma_bf16(C[mi][ni], ah, bh[ni]);
            }
        }
        __syncthreads();
    }
#pragma unroll
    for (int mi = 0; mi < 4; mi++) {
        int r = m0 + wm * 64 + mi * 16 + g;
#pragma unroll
        for (int ni = 0; ni < 4; ni++) {
            int c = n0 + wn * 32 + ni * 8 + 2 * t4;
            if (r < KT) {
                atomicAdd(&d_Tm[r * CINC + c],     C[mi][ni][0]);
                atomicAdd(&d_Tm[r * CINC + c + 1], C[mi][ni][1]);
            }
            if (r + 8 < KT) {
                atomicAdd(&d_Tm[(r + 8) * CINC + c],     C[mi][ni][2]);
                atomicAdd(&d_Tm[(r + 8) * CINC + c + 1], C[mi][ni][3]);
            }
        }
    }
}

// ============ P = T @ Ww : 64x64 tiles, reg double-buffer, split-K 16 ============
// grid (4 Ntiles, 4 Mtiles, 16 Ksplits of 32), block 256
__global__ void __launch_bounds__(256) k_gemmP(const float* __restrict__ Ww) {
    __shared__ float Ast[16][68];
    __shared__ float Bs[16][68];
    int n0 = blockIdx.x * 64;
    int m0 = blockIdx.y * 64;
    int k0 = blockIdx.z * 32;
    int tid = threadIdx.x;
    int tm = tid >> 4, tc = tid & 15;
    int ar = tid >> 2, aq = (tid & 3) * 4;   // A load: row 0..63, k-quad
    int bk = tid >> 4, bn = (tid & 15) * 4;  // B load: k 0..15, n-quad
    float acc[4][4] = {};

    // load chunk 0 into registers
    float4 av0 = (m0 + ar < KT) ? *(const float4*)&d_Tm[(m0 + ar) * CINC + k0 + aq]
                                : make_float4(0.f, 0.f, 0.f, 0.f);
    float4 bv0 = *(const float4*)&Ww[(k0 + bk) * HIDC + n0 + bn];
    // store chunk 0 to smem
    Ast[aq + 0][ar] = av0.x; Ast[aq + 1][ar] = av0.y;
    Ast[aq + 2][ar] = av0.z; Ast[aq + 3][ar] = av0.w;
    *(float4*)&Bs[bk][bn] = bv0;
    // load chunk 1 into registers (overlaps chunk-0 compute after the sync)
    float4 av1 = (m0 + ar < KT) ? *(const float4*)&d_Tm[(m0 + ar) * CINC + k0 + 16 + aq]
                                : make_float4(0.f, 0.f, 0.f, 0.f);
    float4 bv1 = *(const float4*)&Ww[(k0 + 16 + bk) * HIDC + n0 + bn];
    __syncthreads();
#pragma unroll
    for (int kk = 0; kk < 16; kk++) {
        float4 aa = *(const float4*)&Ast[kk][tm * 4];
        float4 bb = *(const float4*)&Bs[kk][tc * 4];
        float a[4] = {aa.x, aa.y, aa.z, aa.w};
        float b[4] = {bb.x, bb.y, bb.z, bb.w};
#pragma unroll
        for (int i = 0; i < 4; i++)
#pragma unroll
            for (int j = 0; j < 4; j++)
                acc[i][j] = fmaf(a[i], b[j], acc[i][j]);
    }
    __syncthreads();
    Ast[aq + 0][ar] = av1.x; Ast[aq + 1][ar] = av1.y;
    Ast[aq + 2][ar] = av1.z; Ast[aq + 3][ar] = av1.w;
    *(float4*)&Bs[bk][bn] = bv1;
    __syncthreads();
#pragma unroll
    for (int kk = 0; kk < 16; kk++) {
        float4 aa = *(const float4*)&Ast[kk][tm * 4];
        float4 bb = *(const float4*)&Bs[kk][tc * 4];
        float a[4] = {aa.x, aa.y, aa.z, aa.w};
        float b[4] = {bb.x, bb.y, bb.z, bb.w};
#pragma unroll
        for (int i = 0; i < 4; i++)
#pragma unroll
            for (int j = 0; j < 4; j++)
                acc[i][j] = fmaf(a[i], b[j], acc[i][j]);
    }
#pragma unroll
    for (int i = 0; i < 4; i++) {
        int r = m0 + tm * 4 + i;
        if (r < KT)
#pragma unroll
            for (int j = 0; j < 4; j++)
                atomicAdd(&d_P[r * HIDC + n0 + tc * 4 + j], acc[i][j]);
    }
}

// ============ hidden = (U*s)@P + Wb : bf16-split3, 2-stage (R8 golden), gate+BN fused ============
__device__ __forceinline__ void h3_load(unsigned aB, unsigned bB,
                                        const float* U,
                                        int st, int kt, int m0, int n0, int tid) {
    int kbase = kt * 16;
    {
        int r = tid >> 2;
        int kcol = (tid & 3) * 4;
        int kk = kbase + kcol;
        int av = (KT - kk) * 4; av = av < 0 ? 0 : (av > 16 ? 16 : av);
        cpa16(aB + (unsigned)(st * 64 * PKA + r * PKA + kcol) * 4u,
              &U[(size_t)(m0 + r) * KT + kk], av);
    }
#pragma unroll
    for (int l = 0; l < 2; l++) {
        int c = tid + 256 * l;
        int r = c >> 5;
        int col = (c & 31) * 4;
        int kk = kbase + r;
        int bv = (kk < KT) ? 16 : 0;
        cpa16(bB + (unsigned)(st * 16 * P132 + r * P132 + col) * 4u,
              &d_P[(size_t)kk * HIDC + n0 + col], bv);
    }
}

__global__ void __launch_bounds__(256, 2) k_gemmH3(const float* __restrict__ U,
                                                   const float* __restrict__ La,
                                                   const float* __restrict__ gW1, const float* __restrict__ gb1,
                                                   const float* __restrict__ gW2, const float* __restrict__ gb2,
                                                   const float* __restrict__ Wb,
                                                   float* __restrict__ hid) {
    extern __shared__ float smf[];
    float* As = smf;                      // [2][64][PKA]
    float* Bs = smf + 2 * 64 * PKA;       // [2][16][P132]
    unsigned aB = smem_u32(As), bB = smem_u32(Bs);
    __shared__ float sS[128], sQ[128];
    __shared__ float s_sm[224];
    __shared__ float stats[EE], gsh[EE];

    int m0 = blockIdx.x * 64;
    int n0 = blockIdx.y * 128;
    int tid = threadIdx.x;
    int w = tid >> 5, lane = tid & 31, g = lane >> 2, t4 = lane & 3;
    int wm = w & 1, wn = w >> 1;

    if (tid < 128) { sS[tid] = 0.f; sQ[tid] = 0.f; }
    if (tid < 224) s_sm[tid] = 0.f;
    if (tid < EE) {
        float s = 0.f;
        for (int i = 0; i < 40; i++) s += La[tid * 40 + i];
        stats[tid] = s * (1.f / 40.f);
    }
    __syncthreads();
    if (tid == 0) {
        float h[EE], g2[EE];
        for (int j = 0; j < EE; j++) {
            float a = gb1[j];
            for (int i = 0; i < EE; i++) a = fmaf(stats[i], gW1[i * EE + j], a);
            h[j] = fmaxf(a, 0.f);
        }
        for (int j = 0; j < EE; j++) {
            float a = gb2[j];
            for (int i = 0; i < EE; i++) a = fmaf(h[i], gW2[i * EE + j], a);
            g2[j] = a;
        }
        float m = g2[0];
        for (int j = 1; j < EE; j++) m = fmaxf(m, g2[j]);
        float se = 0.f;
        for (int j = 0; j < EE; j++) { g2[j] = expf(g2[j] - m); se += g2[j]; }
        for (int j = 0; j < EE; j++) gsh[j] = g2[j] / se;
    }
    __syncthreads();
    if (tid < KT) s_sm[tid] = gsh[tid / 40] * d_Vsum[tid] * (1.f / (float)NT);
    __syncthreads();

    float C[2][4][4];
#pragma unroll
    for (int i = 0; i < 2; i++)
#pragma unroll
        for (int j = 0; j < 4; j++) { C[i][j][0] = C[i][j][1] = C[i][j][2] = C[i][j][3] = 0.f; }

    h3_load(aB, bB, U, 0, 0, m0, n0, tid);
    CP_COMMIT();

    for (int kt = 0; kt < 13; kt++) {
        if (kt < 12) {
            h3_load(aB, bB, U, (kt + 1) & 1, kt + 1, m0, n0, tid);
            CP_COMMIT();
            CP_WAIT1();
        } else {
            CP_WAIT0();
        }
        __syncthreads();
        const float* AsP = As + (kt & 1) * 64 * PKA;
        const float* BsP = Bs + (kt & 1) * 16 * P132;
        int kb = kt * 16;
        float sv0 = s_sm[kb + 2*t4],     sv1 = s_sm[kb + 2*t4 + 1];
        float sv2 = s_sm[kb + 2*t4 + 8], sv3 = s_sm[kb + 2*t4 + 9];
        unsigned bh[4][2], bl[4][2];
#pragma unroll
        for (int ni = 0; ni < 4; ni++) {
            int cn = wn * 32 + ni * 8 + g;
            bsplit(bh[ni][0], bl[ni][0], BsP[(2*t4)   * P132 + cn], BsP[(2*t4+1) * P132 + cn]);
            bsplit(bh[ni][1], bl[ni][1], BsP[(2*t4+8) * P132 + cn], BsP[(2*t4+9) * P132 + cn]);
        }
#pragma unroll
        for (int mi = 0; mi < 2; mi++) {
            int rm = wm * 32 + mi * 16 + g;
            unsigned ah[4], al[4];
            float2 p0 = *(const float2*)&AsP[rm       * PKA + 2*t4];
            float2 p1 = *(const float2*)&AsP[(rm + 8) * PKA + 2*t4];
            float2 p2 = *(const float2*)&AsP[rm       * PKA + 2*t4 + 8];
            float2 p3 = *(const float2*)&AsP[(rm + 8) * PKA + 2*t4 + 8];
            bsplit(ah[0], al[0], p0.x * sv0, p0.y * sv1);
            bsplit(ah[1], al[1], p1.x * sv0, p1.y * sv1);
            bsplit(ah[2], al[2], p2.x * sv2, p2.y * sv3);
            bsplit(ah[3], al[3], p3.x * sv2, p3.y * sv3);
#pragma unroll
            for (int ni = 0; ni < 4; ni++) {
                mma_bf16(C[mi][ni], ah, bl[ni]);
                mma_bf16(C[mi][ni], al, bh[ni]);
                mma_bf16(C[mi][ni], ah, bh[ni]);
            }
        }
        __syncthreads();
    }
    float ls[8] = {}, lq[8] = {};
#pragma unroll
    for (int mi = 0; mi < 2; mi++) {
        int r = m0 + wm * 32 + mi * 16 + g;
#pragma unroll
        for (int ni = 0; ni < 4; ni++) {
            int c = n0 + wn * 32 + ni * 8 + 2 * t4;
            float b0 = Wb[c], b1 = Wb[c + 1];
            float v0 = C[mi][ni][0] + b0, v1 = C[mi][ni][1] + b1;
            float v2 = C[mi][ni][2] + b0, v3 = C[mi][ni][3] + b1;
            hid[r * HIDC + c] = v0;
            hid[r * HIDC + c + 1] = v1;
            hid[(r + 8) * HIDC + c] = v2;
            hid[(r + 8) * HIDC + c + 1] = v3;
            ls[ni * 2]     += v0 + v2;  lq[ni * 2]     += v0 * v0 + v2 * v2;
            ls[ni * 2 + 1] += v1 + v3;  lq[ni * 2 + 1] += v1 * v1 + v3 * v3;
        }
    }
#pragma unroll
    for (int j = 0; j < 8; j++) {
        float a = ls[j], q = lq[j];
        a += __shfl_xor_sync(0xffffffffu, a, 4);
        a += __shfl_xor_sync(0xffffffffu, a, 8);
        a += __shfl_xor_sync(0xffffffffu, a, 16);
        q += __shfl_xor_sync(0xffffffffu, q, 4);
        q += __shfl_xor_sync(0xffffffffu, q, 8);
        q += __shfl_xor_sync(0xffffffffu, q, 16);
        if (g == 0) {
            int c = wn * 32 + (j >> 1) * 8 + 2 * t4 + (j & 1);
            atomicAdd(&sS[c], a);
            atomicAdd(&sQ[c], q);
        }
    }
    __syncthreads();
    if (tid < 128) {
        atomicAdd(&d_colsum[n0 + tid], sS[tid]);
        atomicAdd(&d_colsq[n0 + tid], sQ[tid]);
    }
}

// ---------------- head: BN-finalize fused, 32 rows/block, Mw in smem ----------------
#define HROWS 32
__global__ void __launch_bounds__(256) k_head(const float* __restrict__ hid,
                       const float* __restrict__ gamma, const float* __restrict__ beta,
                       const float* __restrict__ Mw, const float* __restrict__ Mb,
                       float* __restrict__ out) {
    __shared__ float hs[HROWS][HIDC + 4];
    __shared__ float Ms[HIDC * COUTC];
    __shared__ float lg[HROWS][COUTC];
    __shared__ float mu_s[HIDC], rs_s[HIDC];
    int tid = threadIdx.x;
    int n0 = blockIdx.x * HROWS;

    {
        float m = d_colsum[tid] * (1.f / (float)NT);
        float var = d_colsq[tid] * (1.f / (float)NT) - m * m;
        mu_s[tid] = m;
        rs_s[tid] = rsqrtf(var + 1e-5f);
    }
    for (int i = tid; i < HIDC * COUTC; i += 256) Ms[i] = Mw[i];
    __syncthreads();
    for (int i = tid; i < HROWS * HIDC; i += 256) {
        int r = i >> 8, c = i & 255;
        float v = hid[(n0 + r) * HIDC + c];
        v = fmaf((v - mu_s[c]) * rs_s[c], gamma[c], beta[c]);
        hs[r][c] = fmaxf(v, 0.f);
    }
    __syncthreads();

#pragma unroll
    for (int l = 0; l < 5; l++) {
        int idx = tid + 256 * l;
        int r = idx / COUTC, j = idx % COUTC;
        float a = Mb[j];
#pragma unroll 8
        for (int c = 0; c < HIDC; c++) a = fmaf(hs[r][c], Ms[c * COUTC + j], a);
        lg[r][j] = a;
    }
    __syncthreads();

    int w = tid >> 5, lane = tid & 31;
#pragma unroll
    for (int rr = 0; rr < 4; rr++) {
        int r = w * 4 + rr;
        float v0 = (lane < COUTC) ? lg[r][lane] : -1e30f;
        float v1 = (lane + 32 < COUTC) ? lg[r][lane + 32] : -1e30f;
        float m = fmaxf(v0, v1);
#pragma unroll
        for (int off = 16; off; off >>= 1) m = fmaxf(m, __shfl_xor_sync(0xffffffffu, m, off));
        float se = 0.f;
        if (lane < COUTC) se += expf(v0 - m);
        if (lane + 32 < COUTC) se += expf(v1 - m);
#pragma unroll
        for (int off = 16; off; off >>= 1) se += __shfl_xor_sync(0xffffffffu, se, off);
        float lse = m + logf(se);
        if (lane < COUTC) out[(n0 + r) * COUTC + lane] = v0 - lse;
        if (lane + 32 < COUTC) out[(n0 + r) * COUTC + lane + 32] = v1 - lse;
    }
}

// ---------------- launch ----------------
extern "C" void kernel_launch(void* const* d_in, const int* in_sizes, int n_in,
                              void* d_out, int out_size) {
    const float* X     = (const float*)d_in[0];
    const float* La    = (const float*)d_in[1];
    const float* U     = (const float*)d_in[2];
    const float* eW1   = (const float*)d_in[3];
    const float* eb1   = (const float*)d_in[4];
    const float* eW2   = (const float*)d_in[5];
    const float* eb2   = (const float*)d_in[6];
    const float* eW3   = (const float*)d_in[7];
    const float* eb3   = (const float*)d_in[8];
    const float* gW1   = (const float*)d_in[9];
    const float* gb1   = (const float*)d_in[10];
    const float* gW2   = (const float*)d_in[11];
    const float* gb2   = (const float*)d_in[12];
    const float* Ww    = (const float*)d_in[13];
    const float* Wb    = (const float*)d_in[14];
    const float* gamma = (const float*)d_in[15];
    const float* beta  = (const float*)d_in[16];
    const float* Mw    = (const float*)d_in[17];
    const float* Mb    = (const float*)d_in[18];

    float* out_logits = (float*)d_out;
    float* out_hidden = (float*)d_out + (size_t)NT * COUTC;

    const int SMEM_T3 = 2 * 16 * P132 * 2 * 4;              // 33792 B
    const int SMEM_H3 = (2 * 64 * PKA + 2 * 16 * P132) * 4; // 27136 B
    cudaFuncSetAttribute(k_gemmT3, cudaFuncAttributeMaxDynamicSharedMemorySize, SMEM_T3);
    cudaFuncSetAttribute(k_gemmH3, cudaFuncAttributeMaxDynamicSharedMemorySize, SMEM_H3);

    k_table<<<dim3(TGRID / 128, EE), 128>>>(eW1, eb1, eW2, eb2, eW3, eb3);
    k_reduceV<<<NT / 32, 256>>>(U);
    k_gemmT3<<<dim3(2, 4, 32), 256, SMEM_T3>>>(U, X);
    k_gemmP<<<dim3(4, 4, 16), 256>>>(Ww);
    k_gemmH3<<<dim3(128, 2), 256, SMEM_H3>>>(U, La, gW1, gb1, gW2, gb2, Wb, out_hidden);
    k_head<<<NT / HROWS, 256>>>(out_hidden, gamma, beta, Mw, Mb, out_logits);
}

// round 14
// speedup vs baseline: 2.0784x; 1.0915x over previous
#include <cuda_runtime.h>

#define NT    8192
#define KT    200
#define CINC  512
#define HIDC  256
#define COUTC 40
#define EE    5
#define MHD   64
#define TGRID 2048
#define TBL_LO (-8.0f)
#define TBL_HI ( 8.0f)
#define P132  132
#define PKA   20

// ---------------- scratch (single packed struct -> one memset node) ----------------
struct ZBuf {
    float Tm[KT * CINC];    // T = U^T X   [200 x 512]
    float P[KT * HIDC];     // P = T @ Ww  [200 x 256]
    float Vsum[KT];
    float colsum[HIDC];
    float colsq[HIDC];
};
__device__ ZBuf d_Z;
__device__ float d_ftable[EE * TGRID];

// bf16 split-2: (v0,v1) -> hi bf16x2 + lo bf16x2 (lo = residual); v0 in lo16, v1 in hi16
__device__ __forceinline__ void bsplit(unsigned& hi, unsigned& lo, float v0, float v1) {
    unsigned h;
    asm("cvt.rn.bf16x2.f32 %0, %1, %2;" : "=r"(h) : "f"(v1), "f"(v0));
    float r0 = v0 - __uint_as_float(h << 16);
    float r1 = v1 - __uint_as_float(h & 0xffff0000u);
    unsigned l;
    asm("cvt.rn.bf16x2.f32 %0, %1, %2;" : "=r"(l) : "f"(r1), "f"(r0));
    hi = h; lo = l;
}

__device__ __forceinline__ void mma_bf16(float* c, const unsigned* a, const unsigned* b) {
    asm volatile(
        "mma.sync.aligned.m16n8k16.row.col.f32.bf16.bf16.f32 "
        "{%0,%1,%2,%3},{%4,%5,%6,%7},{%8,%9},{%0,%1,%2,%3};"
        : "+f"(c[0]), "+f"(c[1]), "+f"(c[2]), "+f"(c[3])
        : "r"(a[0]), "r"(a[1]), "r"(a[2]), "r"(a[3]), "r"(b[0]), "r"(b[1]));
}

__device__ __forceinline__ unsigned smem_u32(const void* p) {
    return (unsigned)__cvta_generic_to_shared(p);
}
__device__ __forceinline__ void cpa16(unsigned dst, const void* src, int nbytes) {
    asm volatile("cp.async.cg.shared.global [%0], [%1], 16, %2;\n"
                 :: "r"(dst), "l"(src), "r"(nbytes));
}
#define CP_COMMIT() asm volatile("cp.async.commit_group;\n" ::: "memory")
#define CP_WAIT1()  asm volatile("cp.async.wait_group 1;\n" ::: "memory")
#define CP_WAIT0()  asm volatile("cp.async.wait_group 0;\n" ::: "memory")

// ============ K1: table (blocks 0..39)  ||  T3 GEMM (blocks 40..295) ============
__device__ __forceinline__ void t3_load(unsigned aB, unsigned bB,
                                        const float* U, const float* X,
                                        int st, int kt, int zb, int m0, int n0, int tid) {
#pragma unroll
    for (int l = 0; l < 2; l++) {
        int c = tid + 256 * l;
        int r = c >> 5;
        int col = (c & 31) * 4;
        int nb = zb + kt * 16 + r;
        int acol = m0 + col;
        int av = (KT - acol) * 4; av = av < 0 ? 0 : (av > 16 ? 16 : av);
        cpa16(aB + (unsigned)(st * 16 * P132 + r * P132 + col) * 4u,
              &U[(size_t)nb * KT + acol], av);
        cpa16(bB + (unsigned)(st * 16 * P132 + r * P132 + col) * 4u,
              &X[(size_t)nb * CINC + n0 + col], 16);
    }
}

__global__ void __launch_bounds__(256, 2) k_tableT3(
        const float* __restrict__ eW1, const float* __restrict__ eb1,
        const float* __restrict__ eW2, const float* __restrict__ eb2,
        const float* __restrict__ eW3, const float* __restrict__ eb3,
        const float* __restrict__ U, const float* __restrict__ X) {
    extern __shared__ float smf[];
    int tid = threadIdx.x;

    if (blockIdx.x < 40) {
        // ---- table role: 5 experts x 8 chunks of 256 points ----
        int e = blockIdx.x / 8;
        int chunk = blockIdx.x % 8;
        float* W2s = smf;            // 4096
        float* W1s = smf + 4096;     // 64
        float* b1s = smf + 4160;
        float* b2s = smf + 4224;
        float* W3s = smf + 4288;
        for (int i = tid; i < MHD * MHD; i += 256) W2s[i] = eW2[e * MHD * MHD + i];
        if (tid < MHD) {
            W1s[tid] = eW1[e * MHD + tid];
            b1s[tid] = eb1[e * MHD + tid];
            b2s[tid] = eb2[e * MHD + tid];
            W3s[tid] = eW3[e * MHD + tid];
        }
        __syncthreads();

        int t = chunk * 256 + tid;
        float x = TBL_LO + (TBL_HI - TBL_LO) * ((float)t / (float)(TGRID - 1));

        float h1[MHD];
#pragma unroll
        for (int h = 0; h < MHD; h++) h1[h] = fmaxf(fmaf(x, W1s[h], b1s[h]), 0.f);

        float v = eb3[e];
        for (int j = 0; j < MHD; j += 4) {
            float a0 = b2s[j], a1 = b2s[j + 1], a2 = b2s[j + 2], a3 = b2s[j + 3];
#pragma unroll
            for (int h = 0; h < MHD; h++) {
                float hv = h1[h];
                float4 w = *(const float4*)&W2s[h * MHD + j];
                a0 = fmaf(hv, w.x, a0);
                a1 = fmaf(hv, w.y, a1);
                a2 = fmaf(hv, w.z, a2);
                a3 = fmaf(hv, w.w, a3);
            }
            v = fmaf(fmaxf(a0, 0.f), W3s[j],     v);
            v = fmaf(fmaxf(a1, 0.f), W3s[j + 1], v);
            v = fmaf(fmaxf(a2, 0.f), W3s[j + 2], v);
            v = fmaf(fmaxf(a3, 0.f), W3s[j + 3], v);
        }
        d_ftable[e * TGRID + t] = v;
        return;
    }

    // ---- T3 role (R8/R13 golden path) ----
    int b = blockIdx.x - 40;
    int m0 = (b & 1) * 128;
    int n0 = ((b >> 1) & 3) * 128;
    int zb = (b >> 3) * 256;

    float* As = smf;                      // [2][16][P132]
    float* Bs = smf + 2 * 16 * P132;
    unsigned aB = smem_u32(As), bB = smem_u32(Bs);

    int w = tid >> 5, lane = tid & 31, g = lane >> 2, t4 = lane & 3;
    int wm = w & 1, wn = w >> 1;
    float C[4][4][4];
#pragma unroll
    for (int i = 0; i < 4; i++)
#pragma unroll
        for (int j = 0; j < 4; j++) { C[i][j][0] = C[i][j][1] = C[i][j][2] = C[i][j][3] = 0.f; }

    t3_load(aB, bB, U, X, 0, 0, zb, m0, n0, tid);
    CP_COMMIT();

    for (int kt = 0; kt < 16; kt++) {
        if (kt < 15) {
            t3_load(aB, bB, U, X, (kt + 1) & 1, kt + 1, zb, m0, n0, tid);
            CP_COMMIT();
            CP_WAIT1();
        } else {
            CP_WAIT0();
        }
        __syncthreads();
        const float* AsP = As + (kt & 1) * 16 * P132;
        const float* BsP = Bs + (kt & 1) * 16 * P132;
        unsigned bh[4][2], bl[4][2];
#pragma unroll
        for (int ni = 0; ni < 4; ni++) {
            int cn = wn * 32 + ni * 8 + g;
            bsplit(bh[ni][0], bl[ni][0], BsP[(2*t4)   * P132 + cn], BsP[(2*t4+1) * P132 + cn]);
            bsplit(bh[ni][1], bl[ni][1], BsP[(2*t4+8) * P132 + cn], BsP[(2*t4+9) * P132 + cn]);
        }
#pragma unroll
        for (int mi = 0; mi < 4; mi++) {
            int rm = wm * 64 + mi * 16 + g;
            unsigned ah[4], al[4];
            bsplit(ah[0], al[0], AsP[(2*t4)   * P132 + rm],     AsP[(2*t4+1) * P132 + rm]);
            bsplit(ah[1], al[1], AsP[(2*t4)   * P132 + rm + 8], AsP[(2*t4+1) * P132 + rm + 8]);
            bsplit(ah[2], al[2], AsP[(2*t4+8) * P132 + rm],     AsP[(2*t4+9) * P132 + rm]);
            bsplit(ah[3], al[3], AsP[(2*t4+8) * P132 + rm + 8], AsP[(2*t4+9) * P132 + rm + 8]);
#pragma unroll
            for (int ni = 0; ni < 4; ni++) {
                mma_bf16(C[mi][ni], ah, bl[ni]);
                mma_bf16(C[mi][ni], al, bh[ni]);
                mma_bf16(C[mi][ni], ah, bh[ni]);
            }
        }
        __syncthreads();
    }
#pragma unroll
    for (int mi = 0; mi < 4; mi++) {
        int r = m0 + wm * 64 + mi * 16 + g;
#pragma unroll
        for (int ni = 0; ni < 4; ni++) {
            int c = n0 + wn * 32 + ni * 8 + 2 * t4;
            if (r < KT) {
                atomicAdd(&d_Z.Tm[r * CINC + c],     C[mi][ni][0]);
                atomicAdd(&d_Z.Tm[r * CINC + c + 1], C[mi][ni][1]);
            }
            if (r + 8 < KT) {
                atomicAdd(&d_Z.Tm[(r + 8) * CINC + c],     C[mi][ni][2]);
                atomicAdd(&d_Z.Tm[(r + 8) * CINC + c + 1], C[mi][ni][3]);
            }
        }
    }
}

// ============ K2: gemmP (blocks 0..255)  ||  reduceV (blocks 256..511) ============
__global__ void __launch_bounds__(256) k_vP(const float* __restrict__ U,
                                            const float* __restrict__ Ww) {
    int tid = threadIdx.x;
    if (blockIdx.x >= 256) {
        // ---- reduceV role: 32 rows per block ----
        int col = tid;
        if (col >= KT) return;
        int e = col / 40;
        const float* tbl = d_ftable + e * TGRID;
        const float scale = (float)(TGRID - 1) / (TBL_HI - TBL_LO);
        int n0 = (blockIdx.x - 256) * 32;

        float sum = 0.f;
        for (int n = n0; n < n0 + 32; n++) {
            float u  = U[n * KT + col];
            float xi = (u - TBL_LO) * scale;
            xi = fminf(fmaxf(xi, 0.f), (float)(TGRID - 2) + 0.9999f);
            int   i  = (int)xi;
            float fr = xi - (float)i;
            float a = tbl[i], b = tbl[i + 1];
            sum += fmaf(fr, b - a, a);
        }
        atomicAdd(&d_Z.Vsum[col], sum);
        return;
    }

    // ---- gemmP role: 64x64 tiles, reg double-buffer, split-K 16 ----
    __shared__ float Ast[16][68];
    __shared__ float Bs[16][68];
    int bxp = blockIdx.x;
    int n0 = (bxp & 3) * 64;
    int m0 = ((bxp >> 2) & 3) * 64;
    int k0 = (bxp >> 4) * 32;
    int tm = tid >> 4, tc = tid & 15;
    int ar = tid >> 2, aq = (tid & 3) * 4;
    int bk = tid >> 4, bn = (tid & 15) * 4;
    float acc[4][4] = {};

    float4 av0 = (m0 + ar < KT) ? *(const float4*)&d_Z.Tm[(m0 + ar) * CINC + k0 + aq]
                                : make_float4(0.f, 0.f, 0.f, 0.f);
    float4 bv0 = *(const float4*)&Ww[(k0 + bk) * HIDC + n0 + bn];
    Ast[aq + 0][ar] = av0.x; Ast[aq + 1][ar] = av0.y;
    Ast[aq + 2][ar] = av0.z; Ast[aq + 3][ar] = av0.w;
    *(float4*)&Bs[bk][bn] = bv0;
    float4 av1 = (m0 + ar < KT) ? *(const float4*)&d_Z.Tm[(m0 + ar) * CINC + k0 + 16 + aq]
                                : make_float4(0.f, 0.f, 0.f, 0.f);
    float4 bv1 = *(const float4*)&Ww[(k0 + 16 + bk) * HIDC + n0 + bn];
    __syncthreads();
#pragma unroll
    for (int kk = 0; kk < 16; kk++) {
        float4 aa = *(const float4*)&Ast[kk][tm * 4];
        float4 bb = *(const float4*)&Bs[kk][tc * 4];
        float a[4] = {aa.x, aa.y, aa.z, aa.w};
        float b[4] = {bb.x, bb.y, bb.z, bb.w};
#pragma unroll
        for (int i = 0; i < 4; i++)
#pragma unroll
            for (int j = 0; j < 4; j++)
                acc[i][j] = fmaf(a[i], b[j], acc[i][j]);
    }
    __syncthreads();
    Ast[aq + 0][ar] = av1.x; Ast[aq + 1][ar] = av1.y;
    Ast[aq + 2][ar] = av1.z; Ast[aq + 3][ar] = av1.w;
    *(float4*)&Bs[bk][bn] = bv1;
    __syncthreads();
#pragma unroll
    for (int kk = 0; kk < 16; kk++) {
        float4 aa = *(const float4*)&Ast[kk][tm * 4];
        float4 bb = *(const float4*)&Bs[kk][tc * 4];
        float a[4] = {aa.x, aa.y, aa.z, aa.w};
        float b[4] = {bb.x, bb.y, bb.z, bb.w};
#pragma unroll
        for (int i = 0; i < 4; i++)
#pragma unroll
            for (int j = 0; j < 4; j++)
                acc[i][j] = fmaf(a[i], b[j], acc[i][j]);
    }
#pragma unroll
    for (int i = 0; i < 4; i++) {
        int r = m0 + tm * 4 + i;
        if (r < KT)
#pragma unroll
            for (int j = 0; j < 4; j++)
                atomicAdd(&d_Z.P[r * HIDC + n0 + tc * 4 + j], acc[i][j]);
    }
}

// ============ hidden = (U*s)@P + Wb : bf16-split3, 2-stage, gate+BN fused ============
__device__ __forceinline__ void h3_load(unsigned aB, unsigned bB,
                                        const float* U,
                                        int st, int kt, int m0, int n0, int tid) {
    int kbase = kt * 16;
    {
        int r = tid >> 2;
        int kcol = (tid & 3) * 4;
        int kk = kbase + kcol;
        int av = (KT - kk) * 4; av = av < 0 ? 0 : (av > 16 ? 16 : av);
        cpa16(aB + (unsigned)(st * 64 * PKA + r * PKA + kcol) * 4u,
              &U[(size_t)(m0 + r) * KT + kk], av);
    }
#pragma unroll
    for (int l = 0; l < 2; l++) {
        int c = tid + 256 * l;
        int r = c >> 5;
        int col = (c & 31) * 4;
        int kk = kbase + r;
        int bv = (kk < KT) ? 16 : 0;
        cpa16(bB + (unsigned)(st * 16 * P132 + r * P132 + col) * 4u,
              &d_Z.P[(size_t)kk * HIDC + n0 + col], bv);
    }
}

__global__ void __launch_bounds__(256, 2) k_gemmH3(const float* __restrict__ U,
                                                   const float* __restrict__ La,
                                                   const float* __restrict__ gW1, const float* __restrict__ gb1,
                                                   const float* __restrict__ gW2, const float* __restrict__ gb2,
                                                   const float* __restrict__ Wb,
                                                   float* __restrict__ hid) {
    extern __shared__ float smf[];
    float* As = smf;                      // [2][64][PKA]
    float* Bs = smf + 2 * 64 * PKA;       // [2][16][P132]
    unsigned aB = smem_u32(As), bB = smem_u32(Bs);
    __shared__ float sS[128], sQ[128];
    __shared__ float s_sm[224];
    __shared__ float stats[EE], gsh[EE];

    int m0 = blockIdx.x * 64;
    int n0 = blockIdx.y * 128;
    int tid = threadIdx.x;
    int w = tid >> 5, lane = tid & 31, g = lane >> 2, t4 = lane & 3;
    int wm = w & 1, wn = w >> 1;

    if (tid < 128) { sS[tid] = 0.f; sQ[tid] = 0.f; }
    if (tid < 224) s_sm[tid] = 0.f;
    if (tid < EE) {
        float s = 0.f;
        for (int i = 0; i < 40; i++) s += La[tid * 40 + i];
        stats[tid] = s * (1.f / 40.f);
    }
    __syncthreads();
    if (tid == 0) {
        float h[EE], g2[EE];
        for (int j = 0; j < EE; j++) {
            float a = gb1[j];
            for (int i = 0; i < EE; i++) a = fmaf(stats[i], gW1[i * EE + j], a);
            h[j] = fmaxf(a, 0.f);
        }
        for (int j = 0; j < EE; j++) {
            float a = gb2[j];
            for (int i = 0; i < EE; i++) a = fmaf(h[i], gW2[i * EE + j], a);
            g2[j] = a;
        }
        float m = g2[0];
        for (int j = 1; j < EE; j++) m = fmaxf(m, g2[j]);
        float se = 0.f;
        for (int j = 0; j < EE; j++) { g2[j] = expf(g2[j] - m); se += g2[j]; }
        for (int j = 0; j < EE; j++) gsh[j] = g2[j] / se;
    }
    __syncthreads();
    if (tid < KT) s_sm[tid] = gsh[tid / 40] * d_Z.Vsum[tid] * (1.f / (float)NT);
    __syncthreads();

    float C[2][4][4];
#pragma unroll
    for (int i = 0; i < 2; i++)
#pragma unroll
        for (int j = 0; j < 4; j++) { C[i][j][0] = C[i][j][1] = C[i][j][2] = C[i][j][3] = 0.f; }

    h3_load(aB, bB, U, 0, 0, m0, n0, tid);
    CP_COMMIT();

    for (int kt = 0; kt < 13; kt++) {
        if (kt < 12) {
            h3_load(aB, bB, U, (kt + 1) & 1, kt + 1, m0, n0, tid);
            CP_COMMIT();
            CP_WAIT1();
        } else {
            CP_WAIT0();
        }
        __syncthreads();
        const float* AsP = As + (kt & 1) * 64 * PKA;
        const float* BsP = Bs + (kt & 1) * 16 * P132;
        int kb = kt * 16;
        float sv0 = s_sm[kb + 2*t4],     sv1 = s_sm[kb + 2*t4 + 1];
        float sv2 = s_sm[kb + 2*t4 + 8], sv3 = s_sm[kb + 2*t4 + 9];
        unsigned bh[4][2], bl[4][2];
#pragma unroll
        for (int ni = 0; ni < 4; ni++) {
            int cn = wn * 32 + ni * 8 + g;
            bsplit(bh[ni][0], bl[ni][0], BsP[(2*t4)   * P132 + cn], BsP[(2*t4+1) * P132 + cn]);
            bsplit(bh[ni][1], bl[ni][1], BsP[(2*t4+8) * P132 + cn], BsP[(2*t4+9) * P132 + cn]);
        }
#pragma unroll
        for (int mi = 0; mi < 2; mi++) {
            int rm = wm * 32 + mi * 16 + g;
            unsigned ah[4], al[4];
            float2 p0 = *(const float2*)&AsP[rm       * PKA + 2*t4];
            float2 p1 = *(const float2*)&AsP[(rm + 8) * PKA + 2*t4];
            float2 p2 = *(const float2*)&AsP[rm       * PKA + 2*t4 + 8];
            float2 p3 = *(const float2*)&AsP[(rm + 8) * PKA + 2*t4 + 8];
            bsplit(ah[0], al[0], p0.x * sv0, p0.y * sv1);
            bsplit(ah[1], al[1], p1.x * sv0, p1.y * sv1);
            bsplit(ah[2], al[2], p2.x * sv2, p2.y * sv3);
            bsplit(ah[3], al[3], p3.x * sv2, p3.y * sv3);
#pragma unroll
            for (int ni = 0; ni < 4; ni++) {
                mma_bf16(C[mi][ni], ah, bl[ni]);
                mma_bf16(C[mi][ni], al, bh[ni]);
                mma_bf16(C[mi][ni], ah, bh[ni]);
            }
        }
        __syncthreads();
    }
    float ls[8] = {}, lq[8] = {};
#pragma unroll
    for (int mi = 0; mi < 2; mi++) {
        int r = m0 + wm * 32 + mi * 16 + g;
#pragma unroll
        for (int ni = 0; ni < 4; ni++) {
            int c = n0 + wn * 32 + ni * 8 + 2 * t4;
            float b0 = Wb[c], b1 = Wb[c + 1];
            float v0 = C[mi][ni][0] + b0, v1 = C[mi][ni][1] + b1;
            float v2 = C[mi][ni][2] + b0, v3 = C[mi][ni][3] + b1;
            hid[r * HIDC + c] = v0;
            hid[r * HIDC + c + 1] = v1;
            hid[(r + 8) * HIDC + c] = v2;
            hid[(r + 8) * HIDC + c + 1] = v3;
            ls[ni * 2]     += v0 + v2;  lq[ni * 2]     += v0 * v0 + v2 * v2;
            ls[ni * 2 + 1] += v1 + v3;  lq[ni * 2 + 1] += v1 * v1 + v3 * v3;
        }
    }
#pragma unroll
    for (int j = 0; j < 8; j++) {
        float a = ls[j], q = lq[j];
        a += __shfl_xor_sync(0xffffffffu, a, 4);
        a += __shfl_xor_sync(0xffffffffu, a, 8);
        a += __shfl_xor_sync(0xffffffffu, a, 16);
        q += __shfl_xor_sync(0xffffffffu, q, 4);
        q += __shfl_xor_sync(0xffffffffu, q, 8);
        q += __shfl_xor_sync(0xffffffffu, q, 16);
        if (g == 0) {
            int c = wn * 32 + (j >> 1) * 8 + 2 * t4 + (j & 1);
            atomicAdd(&sS[c], a);
            atomicAdd(&sQ[c], q);
        }
    }
    __syncthreads();
    if (tid < 128) {
        atomicAdd(&d_Z.colsum[n0 + tid], sS[tid]);
        atomicAdd(&d_Z.colsq[n0 + tid], sQ[tid]);
    }
}

// ---------------- head: BN-finalize fused, 32 rows/block, Mw in smem ----------------
#define HROWS 32
__global__ void __launch_bounds__(256) k_head(const float* __restrict__ hid,
                       const float* __restrict__ gamma, const float* __restrict__ beta,
                       const float* __restrict__ Mw, const float* __restrict__ Mb,
                       float* __restrict__ out) {
    __shared__ float hs[HROWS][HIDC + 4];
    __shared__ float Ms[HIDC * COUTC];
    __shared__ float lg[HROWS][COUTC];
    __shared__ float mu_s[HIDC], rs_s[HIDC];
    int tid = threadIdx.x;
    int n0 = blockIdx.x * HROWS;

    {
        float m = d_Z.colsum[tid] * (1.f / (float)NT);
        float var = d_Z.colsq[tid] * (1.f / (float)NT) - m * m;
        mu_s[tid] = m;
        rs_s[tid] = rsqrtf(var + 1e-5f);
    }
    for (int i = tid; i < HIDC * COUTC; i += 256) Ms[i] = Mw[i];
    __syncthreads();
    for (int i = tid; i < HROWS * HIDC; i += 256) {
        int r = i >> 8, c = i & 255;
        float v = hid[(n0 + r) * HIDC + c];
        v = fmaf((v - mu_s[c]) * rs_s[c], gamma[c], beta[c]);
        hs[r][c] = fmaxf(v, 0.f);
    }
    __syncthreads();

#pragma unroll
    for (int l = 0; l < 5; l++) {
        int idx = tid + 256 * l;
        int r = idx / COUTC, j = idx % COUTC;
        float a = Mb[j];
#pragma unroll 8
        for (int c = 0; c < HIDC; c++) a = fmaf(hs[r][c], Ms[c * COUTC + j], a);
        lg[r][j] = a;
    }
    __syncthreads();

    int w = tid >> 5, lane = tid & 31;
#pragma unroll
    for (int rr = 0; rr < 4; rr++) {
        int r = w * 4 + rr;
        float v0 = (lane < COUTC) ? lg[r][lane] : -1e30f;
        float v1 = (lane + 32 < COUTC) ? lg[r][lane + 32] : -1e30f;
        float m = fmaxf(v0, v1);
#pragma unroll
        for (int off = 16; off; off >>= 1) m = fmaxf(m, __shfl_xor_sync(0xffffffffu, m, off));
        float se = 0.f;
        if (lane < COUTC) se += expf(v0 - m);
        if (lane + 32 < COUTC) se += expf(v1 - m);
#pragma unroll
        for (int off = 16; off; off >>= 1) se += __shfl_xor_sync(0xffffffffu, se, off);
        float lse = m + logf(se);
        if (lane < COUTC) out[(n0 + r) * COUTC + lane] = v0 - lse;
        if (lane + 32 < COUTC) out[(n0 + r) * COUTC + lane + 32] = v1 - lse;
    }
}

// ---------------- launch ----------------
extern "C" void kernel_launch(void* const* d_in, const int* in_sizes, int n_in,
                              void* d_out, int out_size) {
    const float* X     = (const float*)d_in[0];
    const float* La    = (const float*)d_in[1];
    const float* U     = (const float*)d_in[2];
    const float* eW1   = (const float*)d_in[3];
    const float* eb1   = (const float*)d_in[4];
    const float* eW2   = (const float*)d_in[5];
    const float* eb2   = (const float*)d_in[6];
    const float* eW3   = (const float*)d_in[7];
    const float* eb3   = (const float*)d_in[8];
    const float* gW1   = (const float*)d_in[9];
    const float* gb1   = (const float*)d_in[10];
    const float* gW2   = (const float*)d_in[11];
    const float* gb2   = (const float*)d_in[12];
    const float* Ww    = (const float*)d_in[13];
    const float* Wb    = (const float*)d_in[14];
    const float* gamma = (const float*)d_in[15];
    const float* beta  = (const float*)d_in[16];
    const float* Mw    = (const float*)d_in[17];
    const float* Mb    = (const float*)d_in[18];

    float* out_logits = (float*)d_out;
    float* out_hidden = (float*)d_out + (size_t)NT * COUTC;

    const int SMEM_T3 = 2 * 16 * P132 * 2 * 4;              // 33792 B
    const int SMEM_H3 = (2 * 64 * PKA + 2 * 16 * P132) * 4; // 27136 B
    cudaFuncSetAttribute(k_tableT3, cudaFuncAttributeMaxDynamicSharedMemorySize, SMEM_T3);
    cudaFuncSetAttribute(k_gemmH3, cudaFuncAttributeMaxDynamicSharedMemorySize, SMEM_H3);

    void* zp = nullptr;
    cudaGetSymbolAddress(&zp, d_Z);
    cudaMemsetAsync(zp, 0, sizeof(ZBuf));

    k_tableT3<<<296, 256, SMEM_T3>>>(eW1, eb1, eW2, eb2, eW3, eb3, U, X);
    k_vP<<<512, 256>>>(U, Ww);
    k_gemmH3<<<dim3(128, 2), 256, SMEM_H3>>>(U, La, gW1, gb1, gW2, gb2, Wb, out_hidden);
    k_head<<<NT / HROWS, 256>>>(out_hidden, gamma, beta, Mw, Mb, out_logits);
}

// round 15
// speedup vs baseline: 2.1194x; 1.0197x over previous
#include <cuda_runtime.h>

#define NT    8192
#define KT    200
#define CINC  512
#define HIDC  256
#define COUTC 40
#define EE    5
#define MHD   64
#define TGRID 2048
#define TBL_LO (-8.0f)
#define TBL_HI ( 8.0f)
#define P132  132
#define PKA   20

// ---------------- scratch (single packed struct -> one memset node) ----------------
struct ZBuf {
    float Tm[KT * CINC];    // T = U^T X   [200 x 512]
    float P[KT * HIDC];     // P = T @ Ww  [200 x 256]
    float Vsum[KT];
    float colsum[HIDC];
    float colsq[HIDC];
};
__device__ ZBuf d_Z;
__device__ float d_ftable[EE * TGRID];

// bf16 split-2: (v0,v1) -> hi bf16x2 + lo bf16x2 (lo = residual); v0 in lo16, v1 in hi16
__device__ __forceinline__ void bsplit(unsigned& hi, unsigned& lo, float v0, float v1) {
    unsigned h;
    asm("cvt.rn.bf16x2.f32 %0, %1, %2;" : "=r"(h) : "f"(v1), "f"(v0));
    float r0 = v0 - __uint_as_float(h << 16);
    float r1 = v1 - __uint_as_float(h & 0xffff0000u);
    unsigned l;
    asm("cvt.rn.bf16x2.f32 %0, %1, %2;" : "=r"(l) : "f"(r1), "f"(r0));
    hi = h; lo = l;
}

__device__ __forceinline__ void mma_bf16(float* c, const unsigned* a, const unsigned* b) {
    asm volatile(
        "mma.sync.aligned.m16n8k16.row.col.f32.bf16.bf16.f32 "
        "{%0,%1,%2,%3},{%4,%5,%6,%7},{%8,%9},{%0,%1,%2,%3};"
        : "+f"(c[0]), "+f"(c[1]), "+f"(c[2]), "+f"(c[3])
        : "r"(a[0]), "r"(a[1]), "r"(a[2]), "r"(a[3]), "r"(b[0]), "r"(b[1]));
}

__device__ __forceinline__ unsigned smem_u32(const void* p) {
    return (unsigned)__cvta_generic_to_shared(p);
}
__device__ __forceinline__ void cpa16(unsigned dst, const void* src, int nbytes) {
    asm volatile("cp.async.cg.shared.global [%0], [%1], 16, %2;\n"
                 :: "r"(dst), "l"(src), "r"(nbytes));
}
#define CP_COMMIT() asm volatile("cp.async.commit_group;\n" ::: "memory")
#define CP_WAIT1()  asm volatile("cp.async.wait_group 1;\n" ::: "memory")
#define CP_WAIT0()  asm volatile("cp.async.wait_group 0;\n" ::: "memory")

// ============ K1: table (blocks 0..39)  ||  T3 GEMM (blocks 40..295) ============
__device__ __forceinline__ void t3_load(unsigned aB, unsigned bB,
                                        const float* U, const float* X,
                                        int st, int kt, int zb, int m0, int n0, int tid) {
#pragma unroll
    for (int l = 0; l < 2; l++) {
        int c = tid + 256 * l;
        int r = c >> 5;
        int col = (c & 31) * 4;
        int nb = zb + kt * 16 + r;
        int acol = m0 + col;
        int av = (KT - acol) * 4; av = av < 0 ? 0 : (av > 16 ? 16 : av);
        cpa16(aB + (unsigned)(st * 16 * P132 + r * P132 + col) * 4u,
              &U[(size_t)nb * KT + acol], av);
        cpa16(bB + (unsigned)(st * 16 * P132 + r * P132 + col) * 4u,
              &X[(size_t)nb * CINC + n0 + col], 16);
    }
}

__global__ void __launch_bounds__(256, 2) k_tableT3(
        const float* __restrict__ eW1, const float* __restrict__ eb1,
        const float* __restrict__ eW2, const float* __restrict__ eb2,
        const float* __restrict__ eW3, const float* __restrict__ eb3,
        const float* __restrict__ U, const float* __restrict__ X) {
    extern __shared__ float smf[];
    int tid = threadIdx.x;

    if (blockIdx.x < 40) {
        int e = blockIdx.x / 8;
        int chunk = blockIdx.x % 8;
        float* W2s = smf;
        float* W1s = smf + 4096;
        float* b1s = smf + 4160;
        float* b2s = smf + 4224;
        float* W3s = smf + 4288;
        for (int i = tid; i < MHD * MHD; i += 256) W2s[i] = eW2[e * MHD * MHD + i];
        if (tid < MHD) {
            W1s[tid] = eW1[e * MHD + tid];
            b1s[tid] = eb1[e * MHD + tid];
            b2s[tid] = eb2[e * MHD + tid];
            W3s[tid] = eW3[e * MHD + tid];
        }
        __syncthreads();

        int t = chunk * 256 + tid;
        float x = TBL_LO + (TBL_HI - TBL_LO) * ((float)t / (float)(TGRID - 1));

        float h1[MHD];
#pragma unroll
        for (int h = 0; h < MHD; h++) h1[h] = fmaxf(fmaf(x, W1s[h], b1s[h]), 0.f);

        float v = eb3[e];
        for (int j = 0; j < MHD; j += 4) {
            float a0 = b2s[j], a1 = b2s[j + 1], a2 = b2s[j + 2], a3 = b2s[j + 3];
#pragma unroll
            for (int h = 0; h < MHD; h++) {
                float hv = h1[h];
                float4 w = *(const float4*)&W2s[h * MHD + j];
                a0 = fmaf(hv, w.x, a0);
                a1 = fmaf(hv, w.y, a1);
                a2 = fmaf(hv, w.z, a2);
                a3 = fmaf(hv, w.w, a3);
            }
            v = fmaf(fmaxf(a0, 0.f), W3s[j],     v);
            v = fmaf(fmaxf(a1, 0.f), W3s[j + 1], v);
            v = fmaf(fmaxf(a2, 0.f), W3s[j + 2], v);
            v = fmaf(fmaxf(a3, 0.f), W3s[j + 3], v);
        }
        d_ftable[e * TGRID + t] = v;
        return;
    }

    int b = blockIdx.x - 40;
    int m0 = (b & 1) * 128;
    int n0 = ((b >> 1) & 3) * 128;
    int zb = (b >> 3) * 256;

    float* As = smf;                      // [2][16][P132]
    float* Bs = smf + 2 * 16 * P132;
    unsigned aB = smem_u32(As), bB = smem_u32(Bs);

    int w = tid >> 5, lane = tid & 31, g = lane >> 2, t4 = lane & 3;
    int wm = w & 1, wn = w >> 1;
    float C[4][4][4];
#pragma unroll
    for (int i = 0; i < 4; i++)
#pragma unroll
        for (int j = 0; j < 4; j++) { C[i][j][0] = C[i][j][1] = C[i][j][2] = C[i][j][3] = 0.f; }

    t3_load(aB, bB, U, X, 0, 0, zb, m0, n0, tid);
    CP_COMMIT();

    for (int kt = 0; kt < 16; kt++) {
        if (kt < 15) {
            t3_load(aB, bB, U, X, (kt + 1) & 1, kt + 1, zb, m0, n0, tid);
            CP_COMMIT();
            CP_WAIT1();
        } else {
            CP_WAIT0();
        }
        __syncthreads();
        const float* AsP = As + (kt & 1) * 16 * P132;
        const float* BsP = Bs + (kt & 1) * 16 * P132;
        unsigned bh[4][2], bl[4][2];
#pragma unroll
        for (int ni = 0; ni < 4; ni++) {
            int cn = wn * 32 + ni * 8 + g;
            bsplit(bh[ni][0], bl[ni][0], BsP[(2*t4)   * P132 + cn], BsP[(2*t4+1) * P132 + cn]);
            bsplit(bh[ni][1], bl[ni][1], BsP[(2*t4+8) * P132 + cn], BsP[(2*t4+9) * P132 + cn]);
        }
#pragma unroll
        for (int mi = 0; mi < 4; mi++) {
            int rm = wm * 64 + mi * 16 + g;
            unsigned ah[4], al[4];
            bsplit(ah[0], al[0], AsP[(2*t4)   * P132 + rm],     AsP[(2*t4+1) * P132 + rm]);
            bsplit(ah[1], al[1], AsP[(2*t4)   * P132 + rm + 8], AsP[(2*t4+1) * P132 + rm + 8]);
            bsplit(ah[2], al[2], AsP[(2*t4+8) * P132 + rm],     AsP[(2*t4+9) * P132 + rm]);
            bsplit(ah[3], al[3], AsP[(2*t4+8) * P132 + rm + 8], AsP[(2*t4+9) * P132 + rm + 8]);
#pragma unroll
            for (int ni = 0; ni < 4; ni++) {
                mma_bf16(C[mi][ni], ah, bl[ni]);
                mma_bf16(C[mi][ni], al, bh[ni]);
                mma_bf16(C[mi][ni], ah, bh[ni]);
            }
        }
        __syncthreads();
    }
#pragma unroll
    for (int mi = 0; mi < 4; mi++) {
        int r = m0 + wm * 64 + mi * 16 + g;
#pragma unroll
        for (int ni = 0; ni < 4; ni++) {
            int c = n0 + wn * 32 + ni * 8 + 2 * t4;
            if (r < KT) {
                atomicAdd(&d_Z.Tm[r * CINC + c],     C[mi][ni][0]);
                atomicAdd(&d_Z.Tm[r * CINC + c + 1], C[mi][ni][1]);
            }
            if (r + 8 < KT) {
                atomicAdd(&d_Z.Tm[(r + 8) * CINC + c],     C[mi][ni][2]);
                atomicAdd(&d_Z.Tm[(r + 8) * CINC + c + 1], C[mi][ni][3]);
            }
        }
    }
}

// ============ K2: gemmP (blocks 0..255)  ||  reduceV (blocks 256..511) ============
__global__ void __launch_bounds__(256) k_vP(const float* __restrict__ U,
                                            const float* __restrict__ Ww) {
    int tid = threadIdx.x;
    if (blockIdx.x >= 256) {
        int col = tid;
        if (col >= KT) return;
        int e = col / 40;
        const float* tbl = d_ftable + e * TGRID;
        const float scale = (float)(TGRID - 1) / (TBL_HI - TBL_LO);
        int n0 = (blockIdx.x - 256) * 32;

        float sum = 0.f;
        for (int n = n0; n < n0 + 32; n++) {
            float u  = U[n * KT + col];
            float xi = (u - TBL_LO) * scale;
            xi = fminf(fmaxf(xi, 0.f), (float)(TGRID - 2) + 0.9999f);
            int   i  = (int)xi;
            float fr = xi - (float)i;
            float a = tbl[i], b = tbl[i + 1];
            sum += fmaf(fr, b - a, a);
        }
        atomicAdd(&d_Z.Vsum[col], sum);
        return;
    }

    __shared__ float Ast[16][68];
    __shared__ float Bs[16][68];
    int bxp = blockIdx.x;
    int n0 = (bxp & 3) * 64;
    int m0 = ((bxp >> 2) & 3) * 64;
    int k0 = (bxp >> 4) * 32;
    int tm = tid >> 4, tc = tid & 15;
    int ar = tid >> 2, aq = (tid & 3) * 4;
    int bk = tid >> 4, bn = (tid & 15) * 4;
    float acc[4][4] = {};

    float4 av0 = (m0 + ar < KT) ? *(const float4*)&d_Z.Tm[(m0 + ar) * CINC + k0 + aq]
                                : make_float4(0.f, 0.f, 0.f, 0.f);
    float4 bv0 = *(const float4*)&Ww[(k0 + bk) * HIDC + n0 + bn];
    Ast[aq + 0][ar] = av0.x; Ast[aq + 1][ar] = av0.y;
    Ast[aq + 2][ar] = av0.z; Ast[aq + 3][ar] = av0.w;
    *(float4*)&Bs[bk][bn] = bv0;
    float4 av1 = (m0 + ar < KT) ? *(const float4*)&d_Z.Tm[(m0 + ar) * CINC + k0 + 16 + aq]
                                : make_float4(0.f, 0.f, 0.f, 0.f);
    float4 bv1 = *(const float4*)&Ww[(k0 + 16 + bk) * HIDC + n0 + bn];
    __syncthreads();
#pragma unroll
    for (int kk = 0; kk < 16; kk++) {
        float4 aa = *(const float4*)&Ast[kk][tm * 4];
        float4 bb = *(const float4*)&Bs[kk][tc * 4];
        float a[4] = {aa.x, aa.y, aa.z, aa.w};
        float b[4] = {bb.x, bb.y, bb.z, bb.w};
#pragma unroll
        for (int i = 0; i < 4; i++)
#pragma unroll
            for (int j = 0; j < 4; j++)
                acc[i][j] = fmaf(a[i], b[j], acc[i][j]);
    }
    __syncthreads();
    Ast[aq + 0][ar] = av1.x; Ast[aq + 1][ar] = av1.y;
    Ast[aq + 2][ar] = av1.z; Ast[aq + 3][ar] = av1.w;
    *(float4*)&Bs[bk][bn] = bv1;
    __syncthreads();
#pragma unroll
    for (int kk = 0; kk < 16; kk++) {
        float4 aa = *(const float4*)&Ast[kk][tm * 4];
        float4 bb = *(const float4*)&Bs[kk][tc * 4];
        float a[4] = {aa.x, aa.y, aa.z, aa.w};
        float b[4] = {bb.x, bb.y, bb.z, bb.w};
#pragma unroll
        for (int i = 0; i < 4; i++)
#pragma unroll
            for (int j = 0; j < 4; j++)
                acc[i][j] = fmaf(a[i], b[j], acc[i][j]);
    }
#pragma unroll
    for (int i = 0; i < 4; i++) {
        int r = m0 + tm * 4 + i;
        if (r < KT)
#pragma unroll
            for (int j = 0; j < 4; j++)
                atomicAdd(&d_Z.P[r * HIDC + n0 + tc * 4 + j], acc[i][j]);
    }
}

// ============ hidden = (U*s)@P + Wb : bf16-split3, 2-stage, gate+BN fused ============
__device__ __forceinline__ void h3_load(unsigned aB, unsigned bB,
                                        const float* U,
                                        int st, int kt, int m0, int n0, int tid) {
    int kbase = kt * 16;
    {
        int r = tid >> 2;
        int kcol = (tid & 3) * 4;
        int kk = kbase + kcol;
        int av = (KT - kk) * 4; av = av < 0 ? 0 : (av > 16 ? 16 : av);
        cpa16(aB + (unsigned)(st * 64 * PKA + r * PKA + kcol) * 4u,
              &U[(size_t)(m0 + r) * KT + kk], av);
    }
#pragma unroll
    for (int l = 0; l < 2; l++) {
        int c = tid + 256 * l;
        int r = c >> 5;
        int col = (c & 31) * 4;
        int kk = kbase + r;
        int bv = (kk < KT) ? 16 : 0;
        cpa16(bB + (unsigned)(st * 16 * P132 + r * P132 + col) * 4u,
              &d_Z.P[(size_t)kk * HIDC + n0 + col], bv);
    }
}

__global__ void __launch_bounds__(256, 2) k_gemmH3(const float* __restrict__ U,
                                                   const float* __restrict__ La,
                                                   const float* __restrict__ gW1, const float* __restrict__ gb1,
                                                   const float* __restrict__ gW2, const float* __restrict__ gb2,
                                                   const float* __restrict__ Wb,
                                                   float* __restrict__ hid) {
    extern __shared__ float smf[];
    float* As = smf;                      // [2][64][PKA]
    float* Bs = smf + 2 * 64 * PKA;       // [2][16][P132]
    unsigned aB = smem_u32(As), bB = smem_u32(Bs);
    __shared__ float sS[128], sQ[128];
    __shared__ float s_sm[224];
    __shared__ float stats[EE], gsh[EE];

    int m0 = blockIdx.x * 64;
    int n0 = blockIdx.y * 128;
    int tid = threadIdx.x;
    int w = tid >> 5, lane = tid & 31, g = lane >> 2, t4 = lane & 3;
    int wm = w & 1, wn = w >> 1;

    if (tid < 128) { sS[tid] = 0.f; sQ[tid] = 0.f; }
    if (tid < 224) s_sm[tid] = 0.f;
    if (tid < EE) {
        float s = 0.f;
        for (int i = 0; i < 40; i++) s += La[tid * 40 + i];
        stats[tid] = s * (1.f / 40.f);
    }
    __syncthreads();
    if (tid == 0) {
        float h[EE], g2[EE];
        for (int j = 0; j < EE; j++) {
            float a = gb1[j];
            for (int i = 0; i < EE; i++) a = fmaf(stats[i], gW1[i * EE + j], a);
            h[j] = fmaxf(a, 0.f);
        }
        for (int j = 0; j < EE; j++) {
            float a = gb2[j];
            for (int i = 0; i < EE; i++) a = fmaf(h[i], gW2[i * EE + j], a);
            g2[j] = a;
        }
        float m = g2[0];
        for (int j = 1; j < EE; j++) m = fmaxf(m, g2[j]);
        float se = 0.f;
        for (int j = 0; j < EE; j++) { g2[j] = expf(g2[j] - m); se += g2[j]; }
        for (int j = 0; j < EE; j++) gsh[j] = g2[j] / se;
    }
    __syncthreads();
    if (tid < KT) s_sm[tid] = gsh[tid / 40] * d_Z.Vsum[tid] * (1.f / (float)NT);
    __syncthreads();

    float C[2][4][4];
#pragma unroll
    for (int i = 0; i < 2; i++)
#pragma unroll
        for (int j = 0; j < 4; j++) { C[i][j][0] = C[i][j][1] = C[i][j][2] = C[i][j][3] = 0.f; }

    h3_load(aB, bB, U, 0, 0, m0, n0, tid);
    CP_COMMIT();

    for (int kt = 0; kt < 13; kt++) {
        if (kt < 12) {
            h3_load(aB, bB, U, (kt + 1) & 1, kt + 1, m0, n0, tid);
            CP_COMMIT();
            CP_WAIT1();
        } else {
            CP_WAIT0();
        }
        __syncthreads();
        const float* AsP = As + (kt & 1) * 64 * PKA;
        const float* BsP = Bs + (kt & 1) * 16 * P132;
        int kb = kt * 16;
        float sv0 = s_sm[kb + 2*t4],     sv1 = s_sm[kb + 2*t4 + 1];
        float sv2 = s_sm[kb + 2*t4 + 8], sv3 = s_sm[kb + 2*t4 + 9];
        unsigned bh[4][2], bl[4][2];
#pragma unroll
        for (int ni = 0; ni < 4; ni++) {
            int cn = wn * 32 + ni * 8 + g;
            bsplit(bh[ni][0], bl[ni][0], BsP[(2*t4)   * P132 + cn], BsP[(2*t4+1) * P132 + cn]);
            bsplit(bh[ni][1], bl[ni][1], BsP[(2*t4+8) * P132 + cn], BsP[(2*t4+9) * P132 + cn]);
        }
#pragma unroll
        for (int mi = 0; mi < 2; mi++) {
            int rm = wm * 32 + mi * 16 + g;
            unsigned ah[4], al[4];
            float2 p0 = *(const float2*)&AsP[rm       * PKA + 2*t4];
            float2 p1 = *(const float2*)&AsP[(rm + 8) * PKA + 2*t4];
            float2 p2 = *(const float2*)&AsP[rm       * PKA + 2*t4 + 8];
            float2 p3 = *(const float2*)&AsP[(rm + 8) * PKA + 2*t4 + 8];
            bsplit(ah[0], al[0], p0.x * sv0, p0.y * sv1);
            bsplit(ah[1], al[1], p1.x * sv0, p1.y * sv1);
            bsplit(ah[2], al[2], p2.x * sv2, p2.y * sv3);
            bsplit(ah[3], al[3], p3.x * sv2, p3.y * sv3);
#pragma unroll
            for (int ni = 0; ni < 4; ni++) {
                mma_bf16(C[mi][ni], ah, bl[ni]);
                mma_bf16(C[mi][ni], al, bh[ni]);
                mma_bf16(C[mi][ni], ah, bh[ni]);
            }
        }
        __syncthreads();
    }
    float ls[8] = {}, lq[8] = {};
#pragma unroll
    for (int mi = 0; mi < 2; mi++) {
        int r = m0 + wm * 32 + mi * 16 + g;
#pragma unroll
        for (int ni = 0; ni < 4; ni++) {
            int c = n0 + wn * 32 + ni * 8 + 2 * t4;
            float b0 = Wb[c], b1 = Wb[c + 1];
            float v0 = C[mi][ni][0] + b0, v1 = C[mi][ni][1] + b1;
            float v2 = C[mi][ni][2] + b0, v3 = C[mi][ni][3] + b1;
            hid[r * HIDC + c] = v0;
            hid[r * HIDC + c + 1] = v1;
            hid[(r + 8) * HIDC + c] = v2;
            hid[(r + 8) * HIDC + c + 1] = v3;
            ls[ni * 2]     += v0 + v2;  lq[ni * 2]     += v0 * v0 + v2 * v2;
            ls[ni * 2 + 1] += v1 + v3;  lq[ni * 2 + 1] += v1 * v1 + v3 * v3;
        }
    }
#pragma unroll
    for (int j = 0; j < 8; j++) {
        float a = ls[j], q = lq[j];
        a += __shfl_xor_sync(0xffffffffu, a, 4);
        a += __shfl_xor_sync(0xffffffffu, a, 8);
        a += __shfl_xor_sync(0xffffffffu, a, 16);
        q += __shfl_xor_sync(0xffffffffu, q, 4);
        q += __shfl_xor_sync(0xffffffffu, q, 8);
        q += __shfl_xor_sync(0xffffffffu, q, 16);
        if (g == 0) {
            int c = wn * 32 + (j >> 1) * 8 + 2 * t4 + (j & 1);
            atomicAdd(&sS[c], a);
            atomicAdd(&sQ[c], q);
        }
    }
    __syncthreads();
    if (tid < 128) {
        atomicAdd(&d_Z.colsum[n0 + tid], sS[tid]);
        atomicAdd(&d_Z.colsq[n0 + tid], sQ[tid]);
    }
}

// ---------------- head: transposed Mw in smem, float4 conflict-free dot ----------------
#define HROWS 32
#define PH (HIDC + 4)   // 260 floats: j->j+1 shifts 4 banks; 8-thread phase covers all 32 banks
__global__ void __launch_bounds__(256) k_head(const float* __restrict__ hid,
                       const float* __restrict__ gamma, const float* __restrict__ beta,
                       const float* __restrict__ Mw, const float* __restrict__ Mb,
                       float* __restrict__ out) {
    extern __shared__ float smf[];
    float (*hs)[PH] = (float(*)[PH])smf;                    // [HROWS][PH]
    float (*Mt)[PH] = (float(*)[PH])(smf + HROWS * PH);     // [COUTC][PH], transposed
    __shared__ float lg[HROWS][COUTC];
    __shared__ float mu_s[HIDC], rs_s[HIDC];
    int tid = threadIdx.x;
    int n0 = blockIdx.x * HROWS;

    {
        float m = d_Z.colsum[tid] * (1.f / (float)NT);
        float var = d_Z.colsq[tid] * (1.f / (float)NT) - m * m;
        mu_s[tid] = m;
        rs_s[tid] = rsqrtf(var + 1e-5f);
    }
    // transpose Mw [256x40] -> Mt[j][c]
    for (int i = tid; i < HIDC * COUTC; i += 256) {
        int c = i / COUTC, j = i % COUTC;
        Mt[j][c] = Mw[i];
    }
    __syncthreads();
    for (int i = tid; i < HROWS * HIDC; i += 256) {
        int r = i >> 8, c = i & 255;
        float v = hid[(n0 + r) * HIDC + c];
        v = fmaf((v - mu_s[c]) * rs_s[c], gamma[c], beta[c]);
        hs[r][c] = fmaxf(v, 0.f);
    }
    __syncthreads();

#pragma unroll
    for (int l = 0; l < 5; l++) {
        int idx = tid + 256 * l;
        int r = idx / COUTC, j = idx % COUTC;
        float a = Mb[j];
#pragma unroll 8
        for (int c = 0; c < HIDC; c += 4) {
            float4 h4 = *(const float4*)&hs[r][c];
            float4 m4 = *(const float4*)&Mt[j][c];
            a = fmaf(h4.x, m4.x, a);
            a = fmaf(h4.y, m4.y, a);
            a = fmaf(h4.z, m4.z, a);
            a = fmaf(h4.w, m4.w, a);
        }
        lg[r][j] = a;
    }
    __syncthreads();

    int w = tid >> 5, lane = tid & 31;
#pragma unroll
    for (int rr = 0; rr < 4; rr++) {
        int r = w * 4 + rr;
        float v0 = (lane < COUTC) ? lg[r][lane] : -1e30f;
        float v1 = (lane + 32 < COUTC) ? lg[r][lane + 32] : -1e30f;
        float m = fmaxf(v0, v1);
#pragma unroll
        for (int off = 16; off; off >>= 1) m = fmaxf(m, __shfl_xor_sync(0xffffffffu, m, off));
        float se = 0.f;
        if (lane < COUTC) se += expf(v0 - m);
        if (lane + 32 < COUTC) se += expf(v1 - m);
#pragma unroll
        for (int off = 16; off; off >>= 1) se += __shfl_xor_sync(0xffffffffu, se, off);
        float lse = m + logf(se);
        if (lane < COUTC) out[(n0 + r) * COUTC + lane] = v0 - lse;
        if (lane + 32 < COUTC) out[(n0 + r) * COUTC + lane + 32] = v1 - lse;
    }
}

// ---------------- launch ----------------
extern "C" void kernel_launch(void* const* d_in, const int* in_sizes, int n_in,
                              void* d_out, int out_size) {
    const float* X     = (const float*)d_in[0];
    const float* La    = (const float*)d_in[1];
    const float* U     = (const float*)d_in[2];
    const float* eW1   = (const float*)d_in[3];
    const float* eb1   = (const float*)d_in[4];
    const float* eW2   = (const float*)d_in[5];
    const float* eb2   = (const float*)d_in[6];
    const float* eW3   = (const float*)d_in[7];
    const float* eb3   = (const float*)d_in[8];
    const float* gW1   = (const float*)d_in[9];
    const float* gb1   = (const float*)d_in[10];
    const float* gW2   = (const float*)d_in[11];
    const float* gb2   = (const float*)d_in[12];
    const float* Ww    = (const float*)d_in[13];
    const float* Wb    = (const float*)d_in[14];
    const float* gamma = (const float*)d_in[15];
    const float* beta  = (const float*)d_in[16];
    const float* Mw    = (const float*)d_in[17];
    const float* Mb    = (const float*)d_in[18];

    float* out_logits = (float*)d_out;
    float* out_hidden = (float*)d_out + (size_t)NT * COUTC;

    const int SMEM_T3 = 2 * 16 * P132 * 2 * 4;              // 33792 B
    const int SMEM_H3 = (2 * 64 * PKA + 2 * 16 * P132) * 4; // 27136 B
    const int SMEM_HD = (HROWS + COUTC) * PH * 4;           // 74880 B
    cudaFuncSetAttribute(k_tableT3, cudaFuncAttributeMaxDynamicSharedMemorySize, SMEM_T3);
    cudaFuncSetAttribute(k_gemmH3, cudaFuncAttributeMaxDynamicSharedMemorySize, SMEM_H3);
    cudaFuncSetAttribute(k_head, cudaFuncAttributeMaxDynamicSharedMemorySize, SMEM_HD);

    void* zp = nullptr;
    cudaGetSymbolAddress(&zp, d_Z);
    cudaMemsetAsync(zp, 0, sizeof(ZBuf));

    k_tableT3<<<296, 256, SMEM_T3>>>(eW1, eb1, eW2, eb2, eW3, eb3, U, X);
    k_vP<<<512, 256>>>(U, Ww);
    k_gemmH3<<<dim3(128, 2), 256, SMEM_H3>>>(U, La, gW1, gb1, gW2, gb2, Wb, out_hidden);
    k_head<<<NT / HROWS, 256, SMEM_HD>>>(out_hidden, gamma, beta, Mw, Mb, out_logits);
}